// round 13
// baseline (speedup 1.0000x reference)
#include <cuda_runtime.h>
#include <cuda_bf16.h>
#include <math.h>
#include <stdint.h>

#define BB 32
#define SS 64
#define HH 512
#define TT 32
#define VV 32000
#define TILE_K 32
#define NSLICE 6
#define NCTA 36

// ---------------- device scratch ------------------------------------------------
__device__ float g_Hall[(TT + 1) * BB * HH];
__device__ float g_eu[BB * SS * HH];
__device__ float g_gxe[TT * BB * 3 * HH];
__device__ float g_ctx[BB * 2 * HH];
__device__ float g_part[NSLICE * BB * 3 * HH];
__device__ float g_psum[(size_t)BB * TT * 1024];
__device__ int   g_tok[TT * BB];
__device__ unsigned g_barcnt;
__device__ __nv_bfloat16 g_Hbf[TT * BB * HH];
__device__ __nv_bfloat16 g_Wbf[(size_t)VV * HH];

typedef unsigned long long ull;
__device__ __forceinline__ void ffma2(ull& d, ull a, ull b) {
    asm("fma.rn.f32x2 %0, %1, %2, %0;" : "+l"(d) : "l"(a), "l"(b));
}
__device__ __forceinline__ ull dup2(float x) {
    ull r; asm("mov.b64 %0, {%1, %1};" : "=l"(r) : "f"(x)); return r;
}
__device__ __forceinline__ float2 unpack2(ull v) {
    float2 r; asm("mov.b64 {%0, %1}, %2;" : "=f"(r.x), "=f"(r.y) : "l"(v)); return r;
}
__device__ __forceinline__ float rcpf(float x) {
    float r; asm("rcp.approx.f32 %0, %1;" : "=f"(r) : "f"(x)); return r;
}
__device__ __forceinline__ float sig_f(float x) {
    x = fminf(fmaxf(x, -30.f), 30.f);
    return rcpf(1.f + __expf(-x));
}
__device__ __forceinline__ float tanh_f(float x) {
    x = fminf(fmaxf(x, -15.f), 15.f);
    float e = __expf(2.f * x);
    return 1.f - 2.f * rcpf(e + 1.f);
}
__device__ __forceinline__ uint32_t cvt_bf16x2(float hi, float lo) {
    uint32_t r;
    asm("cvt.rn.bf16x2.f32 %0, %1, %2;" : "=r"(r) : "f"(hi), "f"(lo));
    return r;
}

// mma.sync m16n8k16 bf16 -> f32
__device__ __forceinline__ void mma16816(float* d, const uint32_t* a, const uint32_t* b) {
    asm volatile(
        "mma.sync.aligned.m16n8k16.row.col.f32.bf16.bf16.f32 "
        "{%0,%1,%2,%3}, {%4,%5,%6,%7}, {%8,%9}, {%0,%1,%2,%3};"
        : "+f"(d[0]), "+f"(d[1]), "+f"(d[2]), "+f"(d[3])
        : "r"(a[0]), "r"(a[1]), "r"(a[2]), "r"(a[3]), "r"(b[0]), "r"(b[1]));
}

// ---------------- grid barrier (all NCTA CTAs resident: 1 CTA/SM, 36<=148) -------
__device__ __forceinline__ void gridbar(unsigned target) {
    __syncthreads();
    if (threadIdx.x == 0) {
        __threadfence();
        atomicAdd(&g_barcnt, 1u);
        volatile unsigned* p = &g_barcnt;
        while (*p < target) __nanosleep(32);
    }
    __syncthreads();
}
#define BARG(g) asm volatile("bar.sync %0, %1;" :: "r"((g) + 1), "r"(128) : "memory")

// ---------------- bf16 converts ---------------------------------------------------
__global__ void conv_bf16_kernel(const float* __restrict__ src,
                                 __nv_bfloat16* __restrict__ dst, int n4)
{
    for (int i = blockIdx.x * blockDim.x + threadIdx.x; i < n4; i += gridDim.x * blockDim.x) {
        float4 v = *(const float4*)(src + (size_t)i * 4);
        uint2 o;
        o.x = cvt_bf16x2(v.y, v.x);
        o.y = cvt_bf16x2(v.w, v.z);
        *(uint2*)(dst + (size_t)i * 4) = o;
    }
}

// ---------------- tokens ----------------------------------------------------------
__global__ void tok_kernel(const int* __restrict__ tgt) {
    int i = blockIdx.x * 256 + threadIdx.x;
    if (i < TT * BB) {
        int t = i >> 5, b = i & 31;
        g_tok[i] = (t == 0) ? 0 : tgt[b * TT + t - 1];
    }
}

// ---------------- PERSISTENT recurrence kernel ------------------------------------
// 36 CTAs x 512 threads. Per step:
//   phase A (CTAs 0-31, batch b): gates(t-1 parts)->h_t, q (Wa_w stream),
//     scores (exp identity), softmax, ctx        [proven R9/R10 body]
//   phase B (36 CTAs x 4 named-barrier groups of 128): split-K GRU GEMM,
//     144 groups = 24 n-tiles x 6 k-slices       [proven pgemm body]
__global__ __launch_bounds__(512, 1)
void loop_kernel(const float* __restrict__ Wa_w, const float* __restrict__ Wa_b,
                 const float* __restrict__ Va_w, const float* __restrict__ Va_b,
                 const float* __restrict__ enc, const float* __restrict__ b_hh,
                 const float* __restrict__ W_ih, const float* __restrict__ W_hh,
                 float* __restrict__ attn_out, float* __restrict__ hfin)
{
    __shared__ __align__(16) float sh_h[HH];
    __shared__ __align__(16) float se[HH];
    __shared__ __align__(16) float sva[HH];
    __shared__ float ssc[SS];
    __shared__ float sms[2];
    __shared__ __align__(16) float sxh[4][TILE_K][33];
    __shared__ __align__(16) float sw[4][TILE_K][68];

    const int cta = blockIdx.x;
    const int tid = threadIdx.x;
    const int warp = tid >> 5, lane = tid & 31;
    const int grp = tid >> 7;          // 0..3
    const int gt = tid & 127;          // tid within group
    unsigned ph = 0;

    // phase-B constants for this group
    const int p = cta * 4 + grp;       // 0..143
    const int sB = p / 24;             // 0..5
    const int n0 = (p % 24) * 64;
    const float* wB; int lwB, laB; size_t aOffB;
    if (sB < 4) { wB = W_ih + HH + sB * 256; lwB = 3 * HH; laB = 2 * HH; aOffB = (size_t)sB * 256; }
    else        { wB = W_hh + (sB - 4) * 256; lwB = HH;    laB = HH;     aOffB = (size_t)(sB - 4) * 256; }
    const int lb = gt >> 2, lk = (gt & 3) * 4;
    const int ln = gt >> 3, lk8 = (gt & 7) * 4;
    const int vq = gt & 15, bg = gt >> 4;

    for (int t = 0; t < TT; t++) {
        // ================= phase A =================
        if (cta < BB) {
            const int b = cta;
            if (t > 0) {
                const int j = tid;
                const float* p0 = g_part + (size_t)(0 * BB + b) * (3 * HH);
                const float* p1 = g_part + (size_t)(1 * BB + b) * (3 * HH);
                const float* p2 = g_part + (size_t)(2 * BB + b) * (3 * HH);
                const float* p3 = g_part + (size_t)(3 * BB + b) * (3 * HH);
                const float* p4 = g_part + (size_t)(4 * BB + b) * (3 * HH);
                const float* p5 = g_part + (size_t)(5 * BB + b) * (3 * HH);
                const float* ge = g_gxe + ((size_t)(t - 1) * BB + b) * (3 * HH);
                float gx_r = ge[j] + __ldcg(p0 + j) + __ldcg(p1 + j) + __ldcg(p2 + j) + __ldcg(p3 + j);
                float gh_r = __ldcg(p4 + j) + __ldcg(p5 + j) + b_hh[j];
                float gx_z = ge[j + HH] + __ldcg(p0 + j + HH) + __ldcg(p1 + j + HH) + __ldcg(p2 + j + HH) + __ldcg(p3 + j + HH);
                float gh_z = __ldcg(p4 + j + HH) + __ldcg(p5 + j + HH) + b_hh[j + HH];
                float gx_n = ge[j + 2 * HH] + __ldcg(p0 + j + 2 * HH) + __ldcg(p1 + j + 2 * HH) + __ldcg(p2 + j + 2 * HH) + __ldcg(p3 + j + 2 * HH);
                float gh_n = __ldcg(p4 + j + 2 * HH) + __ldcg(p5 + j + 2 * HH) + b_hh[j + 2 * HH];
                float r = sig_f(gx_r + gh_r);
                float z = sig_f(gx_z + gh_z);
                float n = tanh_f(gx_n + r * gh_n);
                float hp = g_Hall[(size_t)(t - 1) * BB * HH + b * HH + j];
                float hn = (1.f - z) * n + z * hp;
                sh_h[j] = hn;
                g_Hall[(size_t)t * BB * HH + b * HH + j] = hn;
                g_Hbf[(size_t)(t - 1) * BB * HH + b * HH + j] = __float2bfloat16(hn);
            } else {
                sh_h[tid] = g_Hall[b * HH + tid];
            }
            sva[tid] = Va_w[tid];
            __syncthreads();

            // q rows: warp handles rows warp*32..+31
            const float4* sh4 = (const float4*)sh_h;
            for (int rr = 0; rr < 32; rr++) {
                int i = warp * 32 + rr;
                const float4* wrow = (const float4*)(Wa_w + (size_t)i * HH);
                float sum = 0.f;
                #pragma unroll
                for (int it = 0; it < 4; it++) {
                    int idx = lane + 32 * it;
                    float4 w4 = __ldcg(wrow + idx);
                    float4 h4 = sh4[idx];
                    sum += w4.x * h4.x + w4.y * h4.y + w4.z * h4.z + w4.w * h4.w;
                }
                #pragma unroll
                for (int o = 16; o; o >>= 1) sum += __shfl_xor_sync(~0u, sum, o);
                if (lane == 0) se[i] = __expf(2.f * (sum + Wa_b[i]));
            }
            __syncthreads();

            // scores via tanh exp-identity
            const float4* se4 = (const float4*)se;
            const float4* sva4 = (const float4*)sva;
            for (int ss = 0; ss < 4; ss++) {
                int s = warp * 4 + ss;
                const float4* eu = (const float4*)(g_eu + (size_t)(b * SS + s) * HH);
                float sum = 0.f;
                #pragma unroll
                for (int it = 0; it < 4; it++) {
                    int idx = lane + 32 * it;
                    float4 e4 = __ldcg(eu + idx);
                    float4 q4 = se4[idx];
                    float4 v4 = sva4[idx];
                    sum += v4.x * (1.f - 2.f * rcpf(q4.x * e4.x + 1.f));
                    sum += v4.y * (1.f - 2.f * rcpf(q4.y * e4.y + 1.f));
                    sum += v4.z * (1.f - 2.f * rcpf(q4.z * e4.z + 1.f));
                    sum += v4.w * (1.f - 2.f * rcpf(q4.w * e4.w + 1.f));
                }
                #pragma unroll
                for (int o = 16; o; o >>= 1) sum += __shfl_xor_sync(~0u, sum, o);
                if (lane == 0) ssc[s] = sum + Va_b[0];
            }
            __syncthreads();

            if (tid == 0) {
                float m = ssc[0];
                for (int s = 1; s < SS; s++) m = fmaxf(m, ssc[s]);
                float sm = 0.f;
                for (int s = 0; s < SS; s++) sm += __expf(ssc[s] - m);
                sms[0] = m; sms[1] = rcpf(sm);
            }
            __syncthreads();
            if (tid < SS) {
                float w = __expf(ssc[tid] - sms[0]) * sms[1];
                ssc[tid] = w;
                attn_out[((size_t)b * TT + t) * SS + tid] = w;
            }
            __syncthreads();

            for (int kk = tid; kk < 2 * HH; kk += 512) {
                float a = 0.f;
                #pragma unroll 8
                for (int s = 0; s < SS; s++)
                    a += ssc[s] * enc[(size_t)(b * SS + s) * (2 * HH) + kk];
                g_ctx[b * 2 * HH + kk] = a;
            }
        }
        ph++; gridbar(NCTA * ph);

        // ================= phase B: GRU split-K GEMM (4 groups of 128) =========
        {
            const float* aB = (sB < 4) ? (g_ctx + aOffB)
                                       : (g_Hall + (size_t)t * BB * HH + aOffB);
            float4 ra[2], rw[4];
            #pragma unroll
            for (int it = 0; it < 2; it++)
                ra[it] = __ldcg((const float4*)(aB + (size_t)lb * laB + lk + 16 * it));
            #pragma unroll
            for (int it = 0; it < 4; it++)
                rw[it] = *(const float4*)(wB + (size_t)(n0 + ln + 16 * it) * lwB + lk8);

            float acc[4][4] = {};
            #pragma unroll 1
            for (int kt = 0; kt < 8; kt++) {
                #pragma unroll
                for (int it = 0; it < 2; it++) {
                    int kk = lk + 16 * it;
                    sxh[grp][kk + 0][lb] = ra[it].x; sxh[grp][kk + 1][lb] = ra[it].y;
                    sxh[grp][kk + 2][lb] = ra[it].z; sxh[grp][kk + 3][lb] = ra[it].w;
                }
                #pragma unroll
                for (int it = 0; it < 4; it++) {
                    int n = ln + 16 * it;
                    sw[grp][lk8 + 0][n] = rw[it].x; sw[grp][lk8 + 1][n] = rw[it].y;
                    sw[grp][lk8 + 2][n] = rw[it].z; sw[grp][lk8 + 3][n] = rw[it].w;
                }
                BARG(grp);
                if (kt < 7) {
                    int ko = (kt + 1) * TILE_K;
                    #pragma unroll
                    for (int it = 0; it < 2; it++)
                        ra[it] = __ldcg((const float4*)(aB + (size_t)lb * laB + ko + lk + 16 * it));
                    #pragma unroll
                    for (int it = 0; it < 4; it++)
                        rw[it] = *(const float4*)(wB + (size_t)(n0 + ln + 16 * it) * lwB + ko + lk8);
                }
                #pragma unroll 8
                for (int k = 0; k < TILE_K; k++) {
                    float4 wv = *(const float4*)(&sw[grp][k][vq * 4]);
                    float a0 = sxh[grp][k][bg * 4 + 0], a1 = sxh[grp][k][bg * 4 + 1];
                    float a2 = sxh[grp][k][bg * 4 + 2], a3 = sxh[grp][k][bg * 4 + 3];
                    acc[0][0] += wv.x * a0; acc[0][1] += wv.x * a1; acc[0][2] += wv.x * a2; acc[0][3] += wv.x * a3;
                    acc[1][0] += wv.y * a0; acc[1][1] += wv.y * a1; acc[1][2] += wv.y * a2; acc[1][3] += wv.y * a3;
                    acc[2][0] += wv.z * a0; acc[2][1] += wv.z * a1; acc[2][2] += wv.z * a2; acc[2][3] += wv.z * a3;
                    acc[3][0] += wv.w * a0; acc[3][1] += wv.w * a1; acc[3][2] += wv.w * a2; acc[3][3] += wv.w * a3;
                }
                BARG(grp);
            }
            #pragma unroll
            for (int j = 0; j < 4; j++) {
                int b = bg * 4 + j;
                *(float4*)(g_part + ((size_t)sB * BB + b) * (3 * HH) + n0 + vq * 4) =
                    make_float4(acc[0][j], acc[1][j], acc[2][j], acc[3][j]);
            }
        }
        ph++; gridbar(NCTA * ph);
    }

    // ================= final gates: h_32 -> hfin + hbf row 31 =================
    if (cta < BB) {
        const int b = cta, j = tid;
        const float* p0 = g_part + (size_t)(0 * BB + b) * (3 * HH);
        const float* p1 = g_part + (size_t)(1 * BB + b) * (3 * HH);
        const float* p2 = g_part + (size_t)(2 * BB + b) * (3 * HH);
        const float* p3 = g_part + (size_t)(3 * BB + b) * (3 * HH);
        const float* p4 = g_part + (size_t)(4 * BB + b) * (3 * HH);
        const float* p5 = g_part + (size_t)(5 * BB + b) * (3 * HH);
        const float* ge = g_gxe + ((size_t)(TT - 1) * BB + b) * (3 * HH);
        float gx_r = ge[j] + __ldcg(p0 + j) + __ldcg(p1 + j) + __ldcg(p2 + j) + __ldcg(p3 + j);
        float gh_r = __ldcg(p4 + j) + __ldcg(p5 + j) + b_hh[j];
        float gx_z = ge[j + HH] + __ldcg(p0 + j + HH) + __ldcg(p1 + j + HH) + __ldcg(p2 + j + HH) + __ldcg(p3 + j + HH);
        float gh_z = __ldcg(p4 + j + HH) + __ldcg(p5 + j + HH) + b_hh[j + HH];
        float gx_n = ge[j + 2 * HH] + __ldcg(p0 + j + 2 * HH) + __ldcg(p1 + j + 2 * HH) + __ldcg(p2 + j + 2 * HH) + __ldcg(p3 + j + 2 * HH);
        float gh_n = __ldcg(p4 + j + 2 * HH) + __ldcg(p5 + j + 2 * HH) + b_hh[j + 2 * HH];
        float r = sig_f(gx_r + gh_r);
        float z = sig_f(gx_z + gh_z);
        float n = tanh_f(gx_n + r * gh_n);
        float hp = g_Hall[(size_t)(TT - 1) * BB * HH + b * HH + j];
        float hv = (1.f - z) * n + z * hp;
        hfin[b * HH + j] = hv;
        g_Hbf[(size_t)(TT - 1) * BB * HH + b * HH + j] = __float2bfloat16(hv);
    }
}

// ---------------- logits: bf16 HMMA GEMM + fused exp psum -------------------------
#define SPAD 40
__global__ __launch_bounds__(256)
void logits_hmma_kernel(const __nv_bfloat16* __restrict__ Hbf,
                        const __nv_bfloat16* __restrict__ Wbf,
                        const float* __restrict__ out_b,
                        float* __restrict__ logp, float* __restrict__ psum)
{
    __shared__ __align__(16) __nv_bfloat16 sA[128 * SPAD];
    __shared__ __align__(16) __nv_bfloat16 sB[128 * SPAD];
    __shared__ float sbias[128];
    const int tid = threadIdx.x;
    const int wid = tid >> 5, lane = tid & 31;
    const int m0 = blockIdx.x * 128;
    const int n0 = blockIdx.y * 128;
    if (tid < 128) sbias[tid] = out_b[n0 + tid];

    const int lrow = tid >> 2;
    const int lc = tid & 3;
    const __nv_bfloat16* Ag0 = Hbf + (size_t)(m0 + lrow) * HH + lc * 8;
    const __nv_bfloat16* Ag1 = Ag0 + (size_t)64 * HH;
    const __nv_bfloat16* Bg0 = Wbf + (size_t)(n0 + lrow) * HH + lc * 8;
    const __nv_bfloat16* Bg1 = Bg0 + (size_t)64 * HH;
    __nv_bfloat16* sA0 = sA + lrow * SPAD + lc * 8;
    __nv_bfloat16* sA1 = sA0 + 64 * SPAD;
    __nv_bfloat16* sB0 = sB + lrow * SPAD + lc * 8;
    __nv_bfloat16* sB1 = sB0 + 64 * SPAD;

    uint4 ra0 = *(const uint4*)Ag0;
    uint4 ra1 = *(const uint4*)Ag1;
    uint4 rb0 = *(const uint4*)Bg0;
    uint4 rb1 = *(const uint4*)Bg1;

    const int mw = (wid >> 2) * 64, nw = (wid & 3) * 32;
    const int qr = lane >> 2, qc = lane & 3;
    const __nv_bfloat16* pa = sA + (mw + qr) * SPAD + qc * 2;
    const __nv_bfloat16* pb = sB + (nw + qr) * SPAD + qc * 2;

    float acc[4][4][4];
    #pragma unroll
    for (int i = 0; i < 4; i++)
        #pragma unroll
        for (int j = 0; j < 4; j++)
            #pragma unroll
            for (int e = 0; e < 4; e++) acc[i][j][e] = 0.f;

    #pragma unroll 1
    for (int kt = 0; kt < 16; kt++) {
        *(uint4*)sA0 = ra0; *(uint4*)sA1 = ra1;
        *(uint4*)sB0 = rb0; *(uint4*)sB1 = rb1;
        __syncthreads();
        if (kt < 15) {
            ra0 = *(const uint4*)(Ag0 + (kt + 1) * 32);
            ra1 = *(const uint4*)(Ag1 + (kt + 1) * 32);
            rb0 = *(const uint4*)(Bg0 + (kt + 1) * 32);
            rb1 = *(const uint4*)(Bg1 + (kt + 1) * 32);
        }
        #pragma unroll
        for (int ks = 0; ks < 2; ks++) {
            uint32_t af[4][4], bf[4][2];
            #pragma unroll
            for (int mi = 0; mi < 4; mi++) {
                const __nv_bfloat16* p2 = pa + mi * 16 * SPAD + ks * 16;
                af[mi][0] = *(const uint32_t*)(p2);
                af[mi][1] = *(const uint32_t*)(p2 + 8 * SPAD);
                af[mi][2] = *(const uint32_t*)(p2 + 8);
                af[mi][3] = *(const uint32_t*)(p2 + 8 * SPAD + 8);
            }
            #pragma unroll
            for (int ni = 0; ni < 4; ni++) {
                const __nv_bfloat16* p2 = pb + ni * 8 * SPAD + ks * 16;
                bf[ni][0] = *(const uint32_t*)(p2);
                bf[ni][1] = *(const uint32_t*)(p2 + 8);
            }
            #pragma unroll
            for (int mi = 0; mi < 4; mi++)
                #pragma unroll
                for (int ni = 0; ni < 4; ni++)
                    mma16816(acc[mi][ni], af[mi], bf[ni]);
        }
        __syncthreads();
    }

    float es[8];
    #pragma unroll
    for (int i = 0; i < 8; i++) es[i] = 0.f;

    #pragma unroll
    for (int mi = 0; mi < 4; mi++) {
        const int rA = m0 + mw + mi * 16 + qr;
        const int rB = rA + 8;
        const int tqA = rA >> 5, bqA = rA & 31;
        const int tqB = rB >> 5, bqB = rB & 31;
        float* cpA = logp + (size_t)(bqA * TT + tqA) * VV + n0;
        float* cpB = logp + (size_t)(bqB * TT + tqB) * VV + n0;
        #pragma unroll
        for (int ni = 0; ni < 4; ni++) {
            const int cl = nw + ni * 8 + qc * 2;
            float v0 = acc[mi][ni][0] + sbias[cl];
            float v1 = acc[mi][ni][1] + sbias[cl + 1];
            float v2 = acc[mi][ni][2] + sbias[cl];
            float v3 = acc[mi][ni][3] + sbias[cl + 1];
            *(float2*)(cpA + cl) = make_float2(v0, v1);
            *(float2*)(cpB + cl) = make_float2(v2, v3);
            es[mi * 2 + 0] += __expf(v0) + __expf(v1);
            es[mi * 2 + 1] += __expf(v2) + __expf(v3);
        }
    }
    #pragma unroll
    for (int i = 0; i < 8; i++) {
        es[i] += __shfl_xor_sync(0xffffffffu, es[i], 1);
        es[i] += __shfl_xor_sync(0xffffffffu, es[i], 2);
    }
    if (qc == 0) {
        const int col = blockIdx.y * 4 + (wid & 3);
        #pragma unroll
        for (int mi = 0; mi < 4; mi++) {
            int rA = m0 + mw + mi * 16 + qr;
            int rB = rA + 8;
            int rowA = (rA & 31) * TT + (rA >> 5);
            int rowB = (rB & 31) * TT + (rB >> 5);
            psum[(size_t)rowA * 1024 + col] = es[mi * 2 + 0];
            psum[(size_t)rowB * 1024 + col] = es[mi * 2 + 1];
        }
    }
}

// ---------------- fp32 big GEMM (e2u / gxe) ----------------------------------------
__global__ __launch_bounds__(256, 2)
void big128_kernel(const float* __restrict__ A, int lda,
                   const int* __restrict__ tokens,
                   const float* __restrict__ W, int ldw,
                   const float* __restrict__ bias, int K,
                   float* __restrict__ C, int ldc, int mode)
{
    __shared__ __align__(16) float sA[16][132];
    __shared__ __align__(16) float sB[16][132];
    const int tid = threadIdx.x;
    const int m0 = blockIdx.x * 128;
    const int n0 = blockIdx.y * 128;
    const int tx4 = (tid & 15) * 4;
    const int ty4 = (tid >> 4) * 4;

    const int row0 = tid >> 2,         kq0 = (tid & 3) * 4;
    const int row1 = (tid + 256) >> 2;
    long ar0 = tokens ? (long)tokens[m0 + row0] : (long)(m0 + row0);
    long ar1 = tokens ? (long)tokens[m0 + row1] : (long)(m0 + row1);
    const float* ap0 = A + ar0 * lda + kq0;
    const float* ap1 = A + ar1 * lda + kq0;
    const float* wp0 = W + (size_t)(n0 + row0) * ldw + kq0;
    const float* wp1 = W + (size_t)(n0 + row1) * ldw + kq0;

    float4 ra0 = *(const float4*)ap0;
    float4 ra1 = *(const float4*)ap1;
    float4 rw0 = *(const float4*)wp0;
    float4 rw1 = *(const float4*)wp1;

    ull acc[4][8];
    #pragma unroll
    for (int i = 0; i < 4; i++)
        #pragma unroll
        for (int j = 0; j < 8; j++) acc[i][j] = 0ull;

    const int kTiles = K / 16;
    for (int kt = 0; kt < kTiles; kt++) {
        sA[kq0 + 0][row0] = ra0.x; sA[kq0 + 1][row0] = ra0.y;
        sA[kq0 + 2][row0] = ra0.z; sA[kq0 + 3][row0] = ra0.w;
        sA[kq0 + 0][row1] = ra1.x; sA[kq0 + 1][row1] = ra1.y;
        sA[kq0 + 2][row1] = ra1.z; sA[kq0 + 3][row1] = ra1.w;
        sB[kq0 + 0][row0] = rw0.x; sB[kq0 + 1][row0] = rw0.y;
        sB[kq0 + 2][row0] = rw0.z; sB[kq0 + 3][row0] = rw0.w;
        sB[kq0 + 0][row1] = rw1.x; sB[kq0 + 1][row1] = rw1.y;
        sB[kq0 + 2][row1] = rw1.z; sB[kq0 + 3][row1] = rw1.w;
        __syncthreads();
        if (kt + 1 < kTiles) {
            int ko = (kt + 1) * 16;
            ra0 = *(const float4*)(ap0 + ko);
            ra1 = *(const float4*)(ap1 + ko);
            rw0 = *(const float4*)(wp0 + ko);
            rw1 = *(const float4*)(wp1 + ko);
        }
        #pragma unroll
        for (int k = 0; k < 16; k++) {
            ulonglong2 a0 = *(const ulonglong2*)&sA[k][ty4];
            ulonglong2 a1 = *(const ulonglong2*)&sA[k][64 + ty4];
            float4 b0 = *(const float4*)&sB[k][tx4];
            float4 b1 = *(const float4*)&sB[k][64 + tx4];
            ull ap[4] = {a0.x, a0.y, a1.x, a1.y};
            ull bd[8] = {dup2(b0.x), dup2(b0.y), dup2(b0.z), dup2(b0.w),
                         dup2(b1.x), dup2(b1.y), dup2(b1.z), dup2(b1.w)};
            #pragma unroll
            for (int mp = 0; mp < 4; mp++)
                #pragma unroll
                for (int n = 0; n < 8; n++)
                    ffma2(acc[mp][n], ap[mp], bd[n]);
        }
        __syncthreads();
    }

    float4 bs0 = *(const float4*)&bias[n0 + tx4];
    float4 bs1 = *(const float4*)&bias[n0 + 64 + tx4];
    #pragma unroll
    for (int mp = 0; mp < 4; mp++) {
        #pragma unroll
        for (int half = 0; half < 2; half++) {
            int gm = m0 + (mp >> 1) * 64 + ty4 + (mp & 1) * 2 + half;
            float v[8];
            #pragma unroll
            for (int n = 0; n < 8; n++) {
                float2 p = unpack2(acc[mp][n]);
                v[n] = half ? p.y : p.x;
            }
            v[0] += bs0.x; v[1] += bs0.y; v[2] += bs0.z; v[3] += bs0.w;
            v[4] += bs1.x; v[5] += bs1.y; v[6] += bs1.z; v[7] += bs1.w;
            if (mode == 2) {
                #pragma unroll
                for (int n = 0; n < 8; n++) v[n] = __expf(2.f * v[n]);
            }
            float* cp = C + (size_t)gm * ldc + n0;
            *(float4*)(cp + tx4)      = make_float4(v[0], v[1], v[2], v[3]);
            *(float4*)(cp + 64 + tx4) = make_float4(v[4], v[5], v[6], v[7]);
        }
    }
}

// ---------------- small gemm (h0 only) --------------------------------------------
__global__ void gemm_tn_kernel(const float* __restrict__ A, int lda,
                               const float* __restrict__ W, int ldb,
                               float* __restrict__ C, int ldc,
                               const float* __restrict__ bias, int K)
{
    __shared__ float sa[TILE_K][33];
    __shared__ float sb[TILE_K][132];
    const int tid = threadIdx.x;
    const int n0 = blockIdx.x * 128;
    const int vq = tid & 31, bg = tid >> 5;
    const int lm = tid >> 3, lk = (tid & 7) * 4;
    float acc[4][4] = {};
    for (int k0 = 0; k0 < K; k0 += TILE_K) {
        float4 a4 = *(const float4*)(A + (size_t)lm * lda + k0 + lk);
        sa[lk + 0][lm] = a4.x; sa[lk + 1][lm] = a4.y;
        sa[lk + 2][lm] = a4.z; sa[lk + 3][lm] = a4.w;
        #pragma unroll
        for (int it = 0; it < 4; it++) {
            int n = lm + 32 * it;
            float4 b4 = *(const float4*)(W + (size_t)(n0 + n) * ldb + k0 + lk);
            sb[lk + 0][n] = b4.x; sb[lk + 1][n] = b4.y;
            sb[lk + 2][n] = b4.z; sb[lk + 3][n] = b4.w;
        }
        __syncthreads();
        #pragma unroll 8
        for (int k = 0; k < TILE_K; k++) {
            float4 bv = *(const float4*)(&sb[k][vq * 4]);
            float a0 = sa[k][bg * 4 + 0], a1 = sa[k][bg * 4 + 1];
            float a2 = sa[k][bg * 4 + 2], a3 = sa[k][bg * 4 + 3];
            acc[0][0] += bv.x * a0; acc[0][1] += bv.x * a1; acc[0][2] += bv.x * a2; acc[0][3] += bv.x * a3;
            acc[1][0] += bv.y * a0; acc[1][1] += bv.y * a1; acc[1][2] += bv.y * a2; acc[1][3] += bv.y * a3;
            acc[2][0] += bv.z * a0; acc[2][1] += bv.z * a1; acc[2][2] += bv.z * a2; acc[2][3] += bv.z * a3;
            acc[3][0] += bv.w * a0; acc[3][1] += bv.w * a1; acc[3][2] += bv.w * a2; acc[3][3] += bv.w * a3;
        }
        __syncthreads();
    }
    float4 bs4 = *(const float4*)(bias + n0 + vq * 4);
    #pragma unroll
    for (int j = 0; j < 4; j++) {
        float4 o;
        o.x = acc[0][j] + bs4.x; o.y = acc[1][j] + bs4.y;
        o.z = acc[2][j] + bs4.z; o.w = acc[3][j] + bs4.w;
        *(float4*)(C + (size_t)(bg * 4 + j) * ldc + n0 + vq * 4) = o;
    }
}

__global__ void lsm_final_kernel(float* __restrict__ logp)
{
    const int r = blockIdx.x;
    __shared__ float sred[8];
    __shared__ float sls;
    const int tid = threadIdx.x;  // 256
    float s = 0.f;
    for (int i = tid; i < 1000; i += 256)
        s += g_psum[(size_t)r * 1024 + i];
    #pragma unroll
    for (int o = 16; o; o >>= 1) s += __shfl_down_sync(~0u, s, o);
    if ((tid & 31) == 0) sred[tid >> 5] = s;
    __syncthreads();
    if (tid == 0) {
        float tot = 0.f;
        for (int w = 0; w < 8; w++) tot += sred[w];
        sls = logf(tot);
    }
    __syncthreads();
    float ls = sls;
    float* row = logp + (size_t)r * VV;
    for (int i = tid * 4; i < VV; i += 1024) {
        float4 v = *(float4*)(row + i);
        v.x -= ls; v.y -= ls; v.z -= ls; v.w -= ls;
        *(float4*)(row + i) = v;
    }
}

// ---------------- launcher ---------------------------------------------------------
extern "C" void kernel_launch(void* const* d_in, const int* in_sizes, int n_in,
                              void* d_out, int out_size)
{
    const float* enc   = (const float*)d_in[0];
    const float* ehid  = (const float*)d_in[1];
    const int*   tgt   = (const int*)  d_in[2];
    const float* emb   = (const float*)d_in[3];
    const float* Wa_w  = (const float*)d_in[4];
    const float* Wa_b  = (const float*)d_in[5];
    const float* Ua_w  = (const float*)d_in[6];
    const float* Ua_b  = (const float*)d_in[7];
    const float* Va_w  = (const float*)d_in[8];
    const float* Va_b  = (const float*)d_in[9];
    const float* W_ih  = (const float*)d_in[10];
    const float* b_ih  = (const float*)d_in[11];
    const float* W_hh  = (const float*)d_in[12];
    const float* b_hh  = (const float*)d_in[13];
    const float* Wh    = (const float*)d_in[14];
    const float* bh    = (const float*)d_in[15];
    const float* out_w = (const float*)d_in[16];
    const float* out_b = (const float*)d_in[17];

    float* outp = (float*)d_out;
    float* logp = outp;
    float* hfin = outp + (size_t)BB * TT * VV;
    float* attn = hfin + (size_t)BB * HH;

    float *hall, *eu, *gxe, *psum;
    int* tokp;
    unsigned* barp;
    __nv_bfloat16 *hbf, *wbf;
    cudaGetSymbolAddress((void**)&hall, g_Hall);
    cudaGetSymbolAddress((void**)&eu,   g_eu);
    cudaGetSymbolAddress((void**)&gxe,  g_gxe);
    cudaGetSymbolAddress((void**)&psum, g_psum);
    cudaGetSymbolAddress((void**)&tokp, g_tok);
    cudaGetSymbolAddress((void**)&barp, g_barcnt);
    cudaGetSymbolAddress((void**)&hbf,  g_Hbf);
    cudaGetSymbolAddress((void**)&wbf,  g_Wbf);

    cudaMemsetAsync(barp, 0, sizeof(unsigned));
    tok_kernel<<<4, 256>>>(tgt);
    gemm_tn_kernel<<<dim3(4, 1), 256>>>(ehid, 2 * HH, Wh, 2 * HH, hall, HH, bh, 2 * HH);
    big128_kernel<<<dim3(16, 4), 256>>>(enc, 2 * HH, nullptr, Ua_w, 2 * HH, Ua_b,
                                        2 * HH, eu, HH, 2);
    big128_kernel<<<dim3(8, 12), 256>>>(emb, HH, tokp, W_ih, 3 * HH, b_ih,
                                        HH, gxe, 3 * HH, 1);
    conv_bf16_kernel<<<4000, 256>>>(out_w, wbf, VV * HH / 4);

    // whole 32-step recurrence in ONE persistent launch (2 barriers/step)
    loop_kernel<<<NCTA, 512>>>(Wa_w, Wa_b, Va_w, Va_b, enc, b_hh,
                               W_ih, W_hh, attn, hfin);

    logits_hmma_kernel<<<dim3(8, 250), 256>>>(hbf, wbf, out_b, logp, psum);
    lsm_final_kernel<<<BB * TT, 256>>>(logp);
}

// round 14
// speedup vs baseline: 1.4008x; 1.4008x over previous
#include <cuda_runtime.h>
#include <cuda_bf16.h>
#include <math.h>
#include <stdint.h>

#define BB 32
#define SS 64
#define HH 512
#define TT 32
#define VV 32000
#define TILE_K 32
#define NSLICE 6

// ---------------- device scratch ------------------------------------------------
__device__ float g_Hall[(TT + 1) * BB * HH];
__device__ float g_eu[BB * SS * HH];
__device__ float g_gxe[TT * BB * 3 * HH];
__device__ float g_ctx[BB * 2 * HH];
__device__ float g_part[NSLICE * BB * 3 * HH];
__device__ float g_psum[(size_t)BB * TT * 1024];
__device__ int   g_tok[TT * BB];
__device__ __nv_bfloat16 g_Hbf[TT * BB * HH];
__device__ __nv_bfloat16 g_Wbf[(size_t)VV * HH];

typedef unsigned long long ull;
__device__ __forceinline__ void ffma2(ull& d, ull a, ull b) {
    asm("fma.rn.f32x2 %0, %1, %2, %0;" : "+l"(d) : "l"(a), "l"(b));
}
__device__ __forceinline__ ull dup2(float x) {
    ull r; asm("mov.b64 %0, {%1, %1};" : "=l"(r) : "f"(x)); return r;
}
__device__ __forceinline__ float2 unpack2(ull v) {
    float2 r; asm("mov.b64 {%0, %1}, %2;" : "=f"(r.x), "=f"(r.y) : "l"(v)); return r;
}
__device__ __forceinline__ float rcpf(float x) {
    float r; asm("rcp.approx.f32 %0, %1;" : "=f"(r) : "f"(x)); return r;
}
__device__ __forceinline__ float sig_f(float x) {
    x = fminf(fmaxf(x, -30.f), 30.f);
    return rcpf(1.f + __expf(-x));
}
__device__ __forceinline__ float tanh_f(float x) {
    x = fminf(fmaxf(x, -15.f), 15.f);
    float e = __expf(2.f * x);
    return 1.f - 2.f * rcpf(e + 1.f);
}
__device__ __forceinline__ uint32_t cvt_bf16x2(float hi, float lo) {
    uint32_t r;
    asm("cvt.rn.bf16x2.f32 %0, %1, %2;" : "=r"(r) : "f"(hi), "f"(lo));
    return r;
}

// mma.sync m16n8k16 bf16 -> f32
__device__ __forceinline__ void mma16816(float* d, const uint32_t* a, const uint32_t* b) {
    asm volatile(
        "mma.sync.aligned.m16n8k16.row.col.f32.bf16.bf16.f32 "
        "{%0,%1,%2,%3}, {%4,%5,%6,%7}, {%8,%9}, {%0,%1,%2,%3};"
        : "+f"(d[0]), "+f"(d[1]), "+f"(d[2]), "+f"(d[3])
        : "r"(a[0]), "r"(a[1]), "r"(a[2]), "r"(a[3]), "r"(b[0]), "r"(b[1]));
}

// ---------------- bf16 converts ---------------------------------------------------
__global__ void conv_bf16_kernel(const float* __restrict__ src,
                                 __nv_bfloat16* __restrict__ dst, int n4)
{
    for (int i = blockIdx.x * blockDim.x + threadIdx.x; i < n4; i += gridDim.x * blockDim.x) {
        float4 v = *(const float4*)(src + (size_t)i * 4);
        uint2 o;
        o.x = cvt_bf16x2(v.y, v.x);
        o.y = cvt_bf16x2(v.w, v.z);
        *(uint2*)(dst + (size_t)i * 4) = o;
    }
}

// ---------------- tokens ----------------------------------------------------------
__global__ void tok_kernel(const int* __restrict__ tgt) {
    int i = blockIdx.x * 256 + threadIdx.x;
    if (i < TT * BB) {
        int t = i >> 5, b = i & 31;
        g_tok[i] = (t == 0) ? 0 : tgt[b * TT + t - 1];
    }
}

// ---------------- HMMA GEMM from fp32 sources (gxe) --------------------------------
// C[M,N] = A[M,K]@W[N,K]^T + bias, A rows gathered via tokens. Loader converts
// fp32 -> bf16 in registers. Same tile/layout as logits kernel. block 256.
#define SPAD 40
__global__ __launch_bounds__(256)
void hmma_f32src_kernel(const float* __restrict__ A, int lda,
                        const int* __restrict__ tokens,
                        const float* __restrict__ W, int ldw,
                        const float* __restrict__ bias, int K,
                        float* __restrict__ C, int ldc)
{
    __shared__ __align__(16) __nv_bfloat16 sA[128 * SPAD];
    __shared__ __align__(16) __nv_bfloat16 sB[128 * SPAD];
    __shared__ float sbias[128];
    const int tid = threadIdx.x;
    const int wid = tid >> 5, lane = tid & 31;
    const int m0 = blockIdx.x * 128;
    const int n0 = blockIdx.y * 128;
    if (tid < 128) sbias[tid] = bias[n0 + tid];

    const int lrow = tid >> 2;      // 0..63
    const int lc = tid & 3;         // 8-elem chunk
    long ar0 = tokens ? (long)tokens[m0 + lrow] : (long)(m0 + lrow);
    long ar1 = tokens ? (long)tokens[m0 + 64 + lrow] : (long)(m0 + 64 + lrow);
    const float* Ag0 = A + ar0 * lda + lc * 8;
    const float* Ag1 = A + ar1 * lda + lc * 8;
    const float* Bg0 = W + (size_t)(n0 + lrow) * ldw + lc * 8;
    const float* Bg1 = W + (size_t)(n0 + 64 + lrow) * ldw + lc * 8;
    __nv_bfloat16* sA0 = sA + lrow * SPAD + lc * 8;
    __nv_bfloat16* sA1 = sA0 + 64 * SPAD;
    __nv_bfloat16* sB0 = sB + lrow * SPAD + lc * 8;
    __nv_bfloat16* sB1 = sB0 + 64 * SPAD;

    const int mw = (wid >> 2) * 64, nw = (wid & 3) * 32;
    const int qr = lane >> 2, qc = lane & 3;
    const __nv_bfloat16* pa = sA + (mw + qr) * SPAD + qc * 2;
    const __nv_bfloat16* pb = sB + (nw + qr) * SPAD + qc * 2;

    float acc[4][4][4];
    #pragma unroll
    for (int i = 0; i < 4; i++)
        #pragma unroll
        for (int j = 0; j < 4; j++)
            #pragma unroll
            for (int e = 0; e < 4; e++) acc[i][j][e] = 0.f;

    const int kTiles = K / 32;
    #pragma unroll 1
    for (int kt = 0; kt < kTiles; kt++) {
        int ko = kt * 32;
        float4 a0l = *(const float4*)(Ag0 + ko);
        float4 a0h = *(const float4*)(Ag0 + ko + 4);
        float4 a1l = *(const float4*)(Ag1 + ko);
        float4 a1h = *(const float4*)(Ag1 + ko + 4);
        float4 b0l = *(const float4*)(Bg0 + ko);
        float4 b0h = *(const float4*)(Bg0 + ko + 4);
        float4 b1l = *(const float4*)(Bg1 + ko);
        float4 b1h = *(const float4*)(Bg1 + ko + 4);
        uint4 pa0, pa1, pb0, pb1;
        pa0.x = cvt_bf16x2(a0l.y, a0l.x); pa0.y = cvt_bf16x2(a0l.w, a0l.z);
        pa0.z = cvt_bf16x2(a0h.y, a0h.x); pa0.w = cvt_bf16x2(a0h.w, a0h.z);
        pa1.x = cvt_bf16x2(a1l.y, a1l.x); pa1.y = cvt_bf16x2(a1l.w, a1l.z);
        pa1.z = cvt_bf16x2(a1h.y, a1h.x); pa1.w = cvt_bf16x2(a1h.w, a1h.z);
        pb0.x = cvt_bf16x2(b0l.y, b0l.x); pb0.y = cvt_bf16x2(b0l.w, b0l.z);
        pb0.z = cvt_bf16x2(b0h.y, b0h.x); pb0.w = cvt_bf16x2(b0h.w, b0h.z);
        pb1.x = cvt_bf16x2(b1l.y, b1l.x); pb1.y = cvt_bf16x2(b1l.w, b1l.z);
        pb1.z = cvt_bf16x2(b1h.y, b1h.x); pb1.w = cvt_bf16x2(b1h.w, b1h.z);
        *(uint4*)sA0 = pa0; *(uint4*)sA1 = pa1;
        *(uint4*)sB0 = pb0; *(uint4*)sB1 = pb1;
        __syncthreads();
        #pragma unroll
        for (int ks = 0; ks < 2; ks++) {
            uint32_t af[4][4], bf[4][2];
            #pragma unroll
            for (int mi = 0; mi < 4; mi++) {
                const __nv_bfloat16* p2 = pa + mi * 16 * SPAD + ks * 16;
                af[mi][0] = *(const uint32_t*)(p2);
                af[mi][1] = *(const uint32_t*)(p2 + 8 * SPAD);
                af[mi][2] = *(const uint32_t*)(p2 + 8);
                af[mi][3] = *(const uint32_t*)(p2 + 8 * SPAD + 8);
            }
            #pragma unroll
            for (int ni = 0; ni < 4; ni++) {
                const __nv_bfloat16* p2 = pb + ni * 8 * SPAD + ks * 16;
                bf[ni][0] = *(const uint32_t*)(p2);
                bf[ni][1] = *(const uint32_t*)(p2 + 8);
            }
            #pragma unroll
            for (int mi = 0; mi < 4; mi++)
                #pragma unroll
                for (int ni = 0; ni < 4; ni++)
                    mma16816(acc[mi][ni], af[mi], bf[ni]);
        }
        __syncthreads();
    }

    #pragma unroll
    for (int mi = 0; mi < 4; mi++) {
        const int rA = m0 + mw + mi * 16 + qr;
        const int rB = rA + 8;
        float* cpA = C + (size_t)rA * ldc + n0;
        float* cpB = C + (size_t)rB * ldc + n0;
        #pragma unroll
        for (int ni = 0; ni < 4; ni++) {
            const int cl = nw + ni * 8 + qc * 2;
            *(float2*)(cpA + cl) = make_float2(acc[mi][ni][0] + sbias[cl],
                                               acc[mi][ni][1] + sbias[cl + 1]);
            *(float2*)(cpB + cl) = make_float2(acc[mi][ni][2] + sbias[cl],
                                               acc[mi][ni][3] + sbias[cl + 1]);
        }
    }
}

// ---------------- split-K partial GEMM (loop GRU): 6 slices of k=256 ---------------
__global__ void pgemm_kernel(const float* __restrict__ A1, int lda1,
                             const float* __restrict__ W1, int ldw1,
                             const float* __restrict__ A2, int lda2,
                             const float* __restrict__ W2, int ldw2,
                             int slices1, int kPerSlice,
                             float* __restrict__ out, int ldo, int sliceStride)
{
    __shared__ float sxh[TILE_K][33];
    __shared__ float sw[TILE_K][68];
    const int tid = threadIdx.x;
    const int s = blockIdx.y;
    const int n0 = blockIdx.x * 64;
    const float* a; int la; const float* w; int lw;
    if (s < slices1) { a = A1 + s * kPerSlice; la = lda1; w = W1 + s * kPerSlice; lw = ldw1; }
    else { int s2 = s - slices1; a = A2 + s2 * kPerSlice; la = lda2; w = W2 + s2 * kPerSlice; lw = ldw2; }
    const int kTiles = kPerSlice / TILE_K;
    const int lb = tid >> 2, lk = (tid & 3) * 4;
    const int ln = tid >> 3, lk8 = (tid & 7) * 4;
    const int vq = tid & 15, bg = tid >> 4;

    float4 ra[2], rw[4];
    #pragma unroll
    for (int it = 0; it < 2; it++)
        ra[it] = *(const float4*)(a + (size_t)lb * la + lk + 16 * it);
    #pragma unroll
    for (int it = 0; it < 4; it++)
        rw[it] = *(const float4*)(w + (size_t)(n0 + ln + 16 * it) * lw + lk8);

    float acc[4][4] = {};
    for (int kt = 0; kt < kTiles; kt++) {
        #pragma unroll
        for (int it = 0; it < 2; it++) {
            int kk = lk + 16 * it;
            sxh[kk + 0][lb] = ra[it].x; sxh[kk + 1][lb] = ra[it].y;
            sxh[kk + 2][lb] = ra[it].z; sxh[kk + 3][lb] = ra[it].w;
        }
        #pragma unroll
        for (int it = 0; it < 4; it++) {
            int n = ln + 16 * it;
            sw[lk8 + 0][n] = rw[it].x; sw[lk8 + 1][n] = rw[it].y;
            sw[lk8 + 2][n] = rw[it].z; sw[lk8 + 3][n] = rw[it].w;
        }
        __syncthreads();
        if (kt + 1 < kTiles) {
            int ko = (kt + 1) * TILE_K;
            #pragma unroll
            for (int it = 0; it < 2; it++)
                ra[it] = *(const float4*)(a + (size_t)lb * la + ko + lk + 16 * it);
            #pragma unroll
            for (int it = 0; it < 4; it++)
                rw[it] = *(const float4*)(w + (size_t)(n0 + ln + 16 * it) * lw + ko + lk8);
        }
        #pragma unroll 8
        for (int k = 0; k < TILE_K; k++) {
            float4 wv = *(const float4*)(&sw[k][vq * 4]);
            float a0 = sxh[k][bg * 4 + 0], a1 = sxh[k][bg * 4 + 1];
            float a2 = sxh[k][bg * 4 + 2], a3 = sxh[k][bg * 4 + 3];
            acc[0][0] += wv.x * a0; acc[0][1] += wv.x * a1; acc[0][2] += wv.x * a2; acc[0][3] += wv.x * a3;
            acc[1][0] += wv.y * a0; acc[1][1] += wv.y * a1; acc[1][2] += wv.y * a2; acc[1][3] += wv.y * a3;
            acc[2][0] += wv.z * a0; acc[2][1] += wv.z * a1; acc[2][2] += wv.z * a2; acc[2][3] += wv.z * a3;
            acc[3][0] += wv.w * a0; acc[3][1] += wv.w * a1; acc[3][2] += wv.w * a2; acc[3][3] += wv.w * a3;
        }
        __syncthreads();
    }
    #pragma unroll
    for (int j = 0; j < 4; j++) {
        int b = bg * 4 + j;
        *(float4*)(out + (size_t)s * sliceStride + (size_t)b * ldo + n0 + vq * 4) =
            make_float4(acc[0][j], acc[1][j], acc[2][j], acc[3][j]);
    }
}

// ---------------- fused per-step attention (+ previous step's gates) --------------
__global__ void attn_step_kernel(const float* __restrict__ Wa_w,
                                 const float* __restrict__ Wa_b,
                                 const float* __restrict__ Va_w,
                                 const float* __restrict__ Va_b,
                                 const float* __restrict__ enc,
                                 const float* __restrict__ b_hh,
                                 float* __restrict__ attn_out, int t)
{
    __shared__ __align__(16) float sh_h[HH];
    __shared__ __align__(16) float se[HH];
    __shared__ __align__(16) float sva[HH];
    __shared__ float ssc[SS];
    __shared__ float sms[2];
    const int b = blockIdx.x;
    const int tid = threadIdx.x;
    const int warp = tid >> 5, lane = tid & 31;

    if (t > 0) {
        const int j = tid;
        const float* p0 = g_part + (size_t)(0 * BB + b) * (3 * HH);
        const float* p1 = g_part + (size_t)(1 * BB + b) * (3 * HH);
        const float* p2 = g_part + (size_t)(2 * BB + b) * (3 * HH);
        const float* p3 = g_part + (size_t)(3 * BB + b) * (3 * HH);
        const float* p4 = g_part + (size_t)(4 * BB + b) * (3 * HH);
        const float* p5 = g_part + (size_t)(5 * BB + b) * (3 * HH);
        const float* ge = g_gxe + ((size_t)(t - 1) * BB + b) * (3 * HH);
        float gx_r = ge[j] + p0[j] + p1[j] + p2[j] + p3[j];
        float gh_r = p4[j] + p5[j] + b_hh[j];
        float gx_z = ge[j + HH] + p0[j + HH] + p1[j + HH] + p2[j + HH] + p3[j + HH];
        float gh_z = p4[j + HH] + p5[j + HH] + b_hh[j + HH];
        float gx_n = ge[j + 2 * HH] + p0[j + 2 * HH] + p1[j + 2 * HH] + p2[j + 2 * HH] + p3[j + 2 * HH];
        float gh_n = p4[j + 2 * HH] + p5[j + 2 * HH] + b_hh[j + 2 * HH];
        float r = sig_f(gx_r + gh_r);
        float z = sig_f(gx_z + gh_z);
        float n = tanh_f(gx_n + r * gh_n);
        float hp = g_Hall[(size_t)(t - 1) * BB * HH + b * HH + j];
        float hn = (1.f - z) * n + z * hp;
        sh_h[j] = hn;
        g_Hall[(size_t)t * BB * HH + b * HH + j] = hn;
        g_Hbf[(size_t)(t - 1) * BB * HH + b * HH + j] = __float2bfloat16(hn);
    } else {
        sh_h[tid] = g_Hall[b * HH + tid];
    }
    sva[tid] = Va_w[tid];
    __syncthreads();

    // q rows: 2 rows per iteration, Wa_w streamed via __ldcg
    const float4* sh4 = (const float4*)sh_h;
    for (int rr = 0; rr < 32; rr += 2) {
        int i0 = warp * 32 + rr;
        int i1 = i0 + 1;
        const float4* w0 = (const float4*)(Wa_w + (size_t)i0 * HH);
        const float4* w1 = (const float4*)(Wa_w + (size_t)i1 * HH);
        float s0 = 0.f, s1 = 0.f;
        #pragma unroll
        for (int it = 0; it < 4; it++) {
            int idx = lane + 32 * it;
            float4 a0 = __ldcg(w0 + idx);
            float4 a1 = __ldcg(w1 + idx);
            float4 h4 = sh4[idx];
            s0 += a0.x * h4.x + a0.y * h4.y + a0.z * h4.z + a0.w * h4.w;
            s1 += a1.x * h4.x + a1.y * h4.y + a1.z * h4.z + a1.w * h4.w;
        }
        #pragma unroll
        for (int o = 16; o; o >>= 1) {
            s0 += __shfl_xor_sync(~0u, s0, o);
            s1 += __shfl_xor_sync(~0u, s1, o);
        }
        if (lane == 0) {
            se[i0] = __expf(2.f * (s0 + Wa_b[i0]));
            se[i1] = __expf(2.f * (s1 + Wa_b[i1]));
        }
    }
    __syncthreads();

    // scores: 2 s per iteration, eu streamed via __ldcg
    const float4* se4 = (const float4*)se;
    const float4* sva4 = (const float4*)sva;
    for (int ss = 0; ss < 4; ss += 2) {
        int s0i = warp * 4 + ss;
        int s1i = s0i + 1;
        const float4* eu0 = (const float4*)(g_eu + (size_t)(b * SS + s0i) * HH);
        const float4* eu1 = (const float4*)(g_eu + (size_t)(b * SS + s1i) * HH);
        float s0 = 0.f, s1 = 0.f;
        #pragma unroll
        for (int it = 0; it < 4; it++) {
            int idx = lane + 32 * it;
            float4 e0 = __ldcg(eu0 + idx);
            float4 e1 = __ldcg(eu1 + idx);
            float4 q4 = se4[idx];
            float4 v4 = sva4[idx];
            s0 += v4.x * (1.f - 2.f * rcpf(q4.x * e0.x + 1.f));
            s0 += v4.y * (1.f - 2.f * rcpf(q4.y * e0.y + 1.f));
            s0 += v4.z * (1.f - 2.f * rcpf(q4.z * e0.z + 1.f));
            s0 += v4.w * (1.f - 2.f * rcpf(q4.w * e0.w + 1.f));
            s1 += v4.x * (1.f - 2.f * rcpf(q4.x * e1.x + 1.f));
            s1 += v4.y * (1.f - 2.f * rcpf(q4.y * e1.y + 1.f));
            s1 += v4.z * (1.f - 2.f * rcpf(q4.z * e1.z + 1.f));
            s1 += v4.w * (1.f - 2.f * rcpf(q4.w * e1.w + 1.f));
        }
        #pragma unroll
        for (int o = 16; o; o >>= 1) {
            s0 += __shfl_xor_sync(~0u, s0, o);
            s1 += __shfl_xor_sync(~0u, s1, o);
        }
        if (lane == 0) {
            ssc[s0i] = s0 + Va_b[0];
            ssc[s1i] = s1 + Va_b[0];
        }
    }
    __syncthreads();

    if (tid == 0) {
        float m = ssc[0];
        for (int s = 1; s < SS; s++) m = fmaxf(m, ssc[s]);
        float sm = 0.f;
        for (int s = 0; s < SS; s++) sm += __expf(ssc[s] - m);
        sms[0] = m; sms[1] = rcpf(sm);
    }
    __syncthreads();
    if (tid < SS) {
        float w = __expf(ssc[tid] - sms[0]) * sms[1];
        ssc[tid] = w;
        attn_out[((size_t)b * TT + t) * SS + tid] = w;
    }
    __syncthreads();

    for (int kk = tid; kk < 2 * HH; kk += 512) {
        float a = 0.f;
        #pragma unroll 8
        for (int s = 0; s < SS; s++)
            a += ssc[s] * enc[(size_t)(b * SS + s) * (2 * HH) + kk];
        g_ctx[b * 2 * HH + kk] = a;
    }
}

// ---------------- final gates (h_32 -> hfin + hbf) ---------------------------------
__global__ void gates_kernel(const float* __restrict__ gxe_t,
                             const float* __restrict__ b_hh,
                             const float* __restrict__ h_old,
                             __nv_bfloat16* __restrict__ hbf_t,
                             float* __restrict__ hfin)
{
    const int b = blockIdx.x;
    const int j = threadIdx.x;
    const float* p0 = g_part + (size_t)(0 * BB + b) * (3 * HH);
    const float* p1 = g_part + (size_t)(1 * BB + b) * (3 * HH);
    const float* p2 = g_part + (size_t)(2 * BB + b) * (3 * HH);
    const float* p3 = g_part + (size_t)(3 * BB + b) * (3 * HH);
    const float* p4 = g_part + (size_t)(4 * BB + b) * (3 * HH);
    const float* p5 = g_part + (size_t)(5 * BB + b) * (3 * HH);
    const float* ge = gxe_t + (size_t)b * (3 * HH);
    float gx_r = ge[j] + p0[j] + p1[j] + p2[j] + p3[j];
    float gh_r = p4[j] + p5[j] + b_hh[j];
    float gx_z = ge[j + HH] + p0[j + HH] + p1[j + HH] + p2[j + HH] + p3[j + HH];
    float gh_z = p4[j + HH] + p5[j + HH] + b_hh[j + HH];
    float gx_n = ge[j + 2 * HH] + p0[j + 2 * HH] + p1[j + 2 * HH] + p2[j + 2 * HH] + p3[j + 2 * HH];
    float gh_n = p4[j + 2 * HH] + p5[j + 2 * HH] + b_hh[j + 2 * HH];
    float r = sig_f(gx_r + gh_r);
    float z = sig_f(gx_z + gh_z);
    float n = tanh_f(gx_n + r * gh_n);
    float hv = (1.f - z) * n + z * h_old[b * HH + j];
    hbf_t[b * HH + j] = __float2bfloat16(hv);
    hfin[b * HH + j] = hv;
}

// ---------------- logits: bf16 HMMA GEMM + fused exp psum -------------------------
__global__ __launch_bounds__(256)
void logits_hmma_kernel(const __nv_bfloat16* __restrict__ Hbf,
                        const __nv_bfloat16* __restrict__ Wbf,
                        const float* __restrict__ out_b,
                        float* __restrict__ logp, float* __restrict__ psum)
{
    __shared__ __align__(16) __nv_bfloat16 sA[128 * SPAD];
    __shared__ __align__(16) __nv_bfloat16 sB[128 * SPAD];
    __shared__ float sbias[128];
    const int tid = threadIdx.x;
    const int wid = tid >> 5, lane = tid & 31;
    const int m0 = blockIdx.x * 128;
    const int n0 = blockIdx.y * 128;
    if (tid < 128) sbias[tid] = out_b[n0 + tid];

    const int lrow = tid >> 2;
    const int lc = tid & 3;
    const __nv_bfloat16* Ag0 = Hbf + (size_t)(m0 + lrow) * HH + lc * 8;
    const __nv_bfloat16* Ag1 = Ag0 + (size_t)64 * HH;
    const __nv_bfloat16* Bg0 = Wbf + (size_t)(n0 + lrow) * HH + lc * 8;
    const __nv_bfloat16* Bg1 = Bg0 + (size_t)64 * HH;
    __nv_bfloat16* sA0 = sA + lrow * SPAD + lc * 8;
    __nv_bfloat16* sA1 = sA0 + 64 * SPAD;
    __nv_bfloat16* sB0 = sB + lrow * SPAD + lc * 8;
    __nv_bfloat16* sB1 = sB0 + 64 * SPAD;

    uint4 ra0 = *(const uint4*)Ag0;
    uint4 ra1 = *(const uint4*)Ag1;
    uint4 rb0 = *(const uint4*)Bg0;
    uint4 rb1 = *(const uint4*)Bg1;

    const int mw = (wid >> 2) * 64, nw = (wid & 3) * 32;
    const int qr = lane >> 2, qc = lane & 3;
    const __nv_bfloat16* pa = sA + (mw + qr) * SPAD + qc * 2;
    const __nv_bfloat16* pb = sB + (nw + qr) * SPAD + qc * 2;

    float acc[4][4][4];
    #pragma unroll
    for (int i = 0; i < 4; i++)
        #pragma unroll
        for (int j = 0; j < 4; j++)
            #pragma unroll
            for (int e = 0; e < 4; e++) acc[i][j][e] = 0.f;

    #pragma unroll 1
    for (int kt = 0; kt < 16; kt++) {
        *(uint4*)sA0 = ra0; *(uint4*)sA1 = ra1;
        *(uint4*)sB0 = rb0; *(uint4*)sB1 = rb1;
        __syncthreads();
        if (kt < 15) {
            ra0 = *(const uint4*)(Ag0 + (kt + 1) * 32);
            ra1 = *(const uint4*)(Ag1 + (kt + 1) * 32);
            rb0 = *(const uint4*)(Bg0 + (kt + 1) * 32);
            rb1 = *(const uint4*)(Bg1 + (kt + 1) * 32);
        }
        #pragma unroll
        for (int ks = 0; ks < 2; ks++) {
            uint32_t af[4][4], bf[4][2];
            #pragma unroll
            for (int mi = 0; mi < 4; mi++) {
                const __nv_bfloat16* p2 = pa + mi * 16 * SPAD + ks * 16;
                af[mi][0] = *(const uint32_t*)(p2);
                af[mi][1] = *(const uint32_t*)(p2 + 8 * SPAD);
                af[mi][2] = *(const uint32_t*)(p2 + 8);
                af[mi][3] = *(const uint32_t*)(p2 + 8 * SPAD + 8);
            }
            #pragma unroll
            for (int ni = 0; ni < 4; ni++) {
                const __nv_bfloat16* p2 = pb + ni * 8 * SPAD + ks * 16;
                bf[ni][0] = *(const uint32_t*)(p2);
                bf[ni][1] = *(const uint32_t*)(p2 + 8);
            }
            #pragma unroll
            for (int mi = 0; mi < 4; mi++)
                #pragma unroll
                for (int ni = 0; ni < 4; ni++)
                    mma16816(acc[mi][ni], af[mi], bf[ni]);
        }
        __syncthreads();
    }

    float es[8];
    #pragma unroll
    for (int i = 0; i < 8; i++) es[i] = 0.f;

    #pragma unroll
    for (int mi = 0; mi < 4; mi++) {
        const int rA = m0 + mw + mi * 16 + qr;
        const int rB = rA + 8;
        const int tqA = rA >> 5, bqA = rA & 31;
        const int tqB = rB >> 5, bqB = rB & 31;
        float* cpA = logp + (size_t)(bqA * TT + tqA) * VV + n0;
        float* cpB = logp + (size_t)(bqB * TT + tqB) * VV + n0;
        #pragma unroll
        for (int ni = 0; ni < 4; ni++) {
            const int cl = nw + ni * 8 + qc * 2;
            float v0 = acc[mi][ni][0] + sbias[cl];
            float v1 = acc[mi][ni][1] + sbias[cl + 1];
            float v2 = acc[mi][ni][2] + sbias[cl];
            float v3 = acc[mi][ni][3] + sbias[cl + 1];
            *(float2*)(cpA + cl) = make_float2(v0, v1);
            *(float2*)(cpB + cl) = make_float2(v2, v3);
            es[mi * 2 + 0] += __expf(v0) + __expf(v1);
            es[mi * 2 + 1] += __expf(v2) + __expf(v3);
        }
    }
    #pragma unroll
    for (int i = 0; i < 8; i++) {
        es[i] += __shfl_xor_sync(0xffffffffu, es[i], 1);
        es[i] += __shfl_xor_sync(0xffffffffu, es[i], 2);
    }
    if (qc == 0) {
        const int col = blockIdx.y * 4 + (wid & 3);
        #pragma unroll
        for (int mi = 0; mi < 4; mi++) {
            int rA = m0 + mw + mi * 16 + qr;
            int rB = rA + 8;
            int rowA = (rA & 31) * TT + (rA >> 5);
            int rowB = (rB & 31) * TT + (rB >> 5);
            psum[(size_t)rowA * 1024 + col] = es[mi * 2 + 0];
            psum[(size_t)rowB * 1024 + col] = es[mi * 2 + 1];
        }
    }
}

// ---------------- fp32 big GEMM (e2u only) -----------------------------------------
__global__ __launch_bounds__(256, 2)
void big128_kernel(const float* __restrict__ A, int lda,
                   const float* __restrict__ W, int ldw,
                   const float* __restrict__ bias, int K,
                   float* __restrict__ C, int ldc, int mode)
{
    __shared__ __align__(16) float sA[16][132];
    __shared__ __align__(16) float sB[16][132];
    const int tid = threadIdx.x;
    const int m0 = blockIdx.x * 128;
    const int n0 = blockIdx.y * 128;
    const int tx4 = (tid & 15) * 4;
    const int ty4 = (tid >> 4) * 4;

    const int row0 = tid >> 2,         kq0 = (tid & 3) * 4;
    const int row1 = (tid + 256) >> 2;
    const float* ap0 = A + (size_t)(m0 + row0) * lda + kq0;
    const float* ap1 = A + (size_t)(m0 + row1) * lda + kq0;
    const float* wp0 = W + (size_t)(n0 + row0) * ldw + kq0;
    const float* wp1 = W + (size_t)(n0 + row1) * ldw + kq0;

    float4 ra0 = *(const float4*)ap0;
    float4 ra1 = *(const float4*)ap1;
    float4 rw0 = *(const float4*)wp0;
    float4 rw1 = *(const float4*)wp1;

    ull acc[4][8];
    #pragma unroll
    for (int i = 0; i < 4; i++)
        #pragma unroll
        for (int j = 0; j < 8; j++) acc[i][j] = 0ull;

    const int kTiles = K / 16;
    for (int kt = 0; kt < kTiles; kt++) {
        sA[kq0 + 0][row0] = ra0.x; sA[kq0 + 1][row0] = ra0.y;
        sA[kq0 + 2][row0] = ra0.z; sA[kq0 + 3][row0] = ra0.w;
        sA[kq0 + 0][row1] = ra1.x; sA[kq0 + 1][row1] = ra1.y;
        sA[kq0 + 2][row1] = ra1.z; sA[kq0 + 3][row1] = ra1.w;
        sB[kq0 + 0][row0] = rw0.x; sB[kq0 + 1][row0] = rw0.y;
        sB[kq0 + 2][row0] = rw0.z; sB[kq0 + 3][row0] = rw0.w;
        sB[kq0 + 0][row1] = rw1.x; sB[kq0 + 1][row1] = rw1.y;
        sB[kq0 + 2][row1] = rw1.z; sB[kq0 + 3][row1] = rw1.w;
        __syncthreads();
        if (kt + 1 < kTiles) {
            int ko = (kt + 1) * 16;
            ra0 = *(const float4*)(ap0 + ko);
            ra1 = *(const float4*)(ap1 + ko);
            rw0 = *(const float4*)(wp0 + ko);
            rw1 = *(const float4*)(wp1 + ko);
        }
        #pragma unroll
        for (int k = 0; k < 16; k++) {
            ulonglong2 a0 = *(const ulonglong2*)&sA[k][ty4];
            ulonglong2 a1 = *(const ulonglong2*)&sA[k][64 + ty4];
            float4 b0 = *(const float4*)&sB[k][tx4];
            float4 b1 = *(const float4*)&sB[k][64 + tx4];
            ull ap[4] = {a0.x, a0.y, a1.x, a1.y};
            ull bd[8] = {dup2(b0.x), dup2(b0.y), dup2(b0.z), dup2(b0.w),
                         dup2(b1.x), dup2(b1.y), dup2(b1.z), dup2(b1.w)};
            #pragma unroll
            for (int mp = 0; mp < 4; mp++)
                #pragma unroll
                for (int n = 0; n < 8; n++)
                    ffma2(acc[mp][n], ap[mp], bd[n]);
        }
        __syncthreads();
    }

    float4 bs0 = *(const float4*)&bias[n0 + tx4];
    float4 bs1 = *(const float4*)&bias[n0 + 64 + tx4];
    #pragma unroll
    for (int mp = 0; mp < 4; mp++) {
        #pragma unroll
        for (int half = 0; half < 2; half++) {
            int gm = m0 + (mp >> 1) * 64 + ty4 + (mp & 1) * 2 + half;
            float v[8];
            #pragma unroll
            for (int n = 0; n < 8; n++) {
                float2 p = unpack2(acc[mp][n]);
                v[n] = half ? p.y : p.x;
            }
            v[0] += bs0.x; v[1] += bs0.y; v[2] += bs0.z; v[3] += bs0.w;
            v[4] += bs1.x; v[5] += bs1.y; v[6] += bs1.z; v[7] += bs1.w;
            if (mode == 2) {
                #pragma unroll
                for (int n = 0; n < 8; n++) v[n] = __expf(2.f * v[n]);
            }
            float* cp = C + (size_t)gm * ldc + n0;
            *(float4*)(cp + tx4)      = make_float4(v[0], v[1], v[2], v[3]);
            *(float4*)(cp + 64 + tx4) = make_float4(v[4], v[5], v[6], v[7]);
        }
    }
}

// ---------------- small gemm (h0 only) --------------------------------------------
__global__ void gemm_tn_kernel(const float* __restrict__ A, int lda,
                               const float* __restrict__ W, int ldb,
                               float* __restrict__ C, int ldc,
                               const float* __restrict__ bias, int K)
{
    __shared__ float sa[TILE_K][33];
    __shared__ float sb[TILE_K][132];
    const int tid = threadIdx.x;
    const int n0 = blockIdx.x * 128;
    const int vq = tid & 31, bg = tid >> 5;
    const int lm = tid >> 3, lk = (tid & 7) * 4;
    float acc[4][4] = {};
    for (int k0 = 0; k0 < K; k0 += TILE_K) {
        float4 a4 = *(const float4*)(A + (size_t)lm * lda + k0 + lk);
        sa[lk + 0][lm] = a4.x; sa[lk + 1][lm] = a4.y;
        sa[lk + 2][lm] = a4.z; sa[lk + 3][lm] = a4.w;
        #pragma unroll
        for (int it = 0; it < 4; it++) {
            int n = lm + 32 * it;
            float4 b4 = *(const float4*)(W + (size_t)(n0 + n) * ldb + k0 + lk);
            sb[lk + 0][n] = b4.x; sb[lk + 1][n] = b4.y;
            sb[lk + 2][n] = b4.z; sb[lk + 3][n] = b4.w;
        }
        __syncthreads();
        #pragma unroll 8
        for (int k = 0; k < TILE_K; k++) {
            float4 bv = *(const float4*)(&sb[k][vq * 4]);
            float a0 = sa[k][bg * 4 + 0], a1 = sa[k][bg * 4 + 1];
            float a2 = sa[k][bg * 4 + 2], a3 = sa[k][bg * 4 + 3];
            acc[0][0] += bv.x * a0; acc[0][1] += bv.x * a1; acc[0][2] += bv.x * a2; acc[0][3] += bv.x * a3;
            acc[1][0] += bv.y * a0; acc[1][1] += bv.y * a1; acc[1][2] += bv.y * a2; acc[1][3] += bv.y * a3;
            acc[2][0] += bv.z * a0; acc[2][1] += bv.z * a1; acc[2][2] += bv.z * a2; acc[2][3] += bv.z * a3;
            acc[3][0] += bv.w * a0; acc[3][1] += bv.w * a1; acc[3][2] += bv.w * a2; acc[3][3] += bv.w * a3;
        }
        __syncthreads();
    }
    float4 bs4 = *(const float4*)(bias + n0 + vq * 4);
    #pragma unroll
    for (int j = 0; j < 4; j++) {
        float4 o;
        o.x = acc[0][j] + bs4.x; o.y = acc[1][j] + bs4.y;
        o.z = acc[2][j] + bs4.z; o.w = acc[3][j] + bs4.w;
        *(float4*)(C + (size_t)(bg * 4 + j) * ldc + n0 + vq * 4) = o;
    }
}

__global__ void lsm_final_kernel(float* __restrict__ logp)
{
    const int r = blockIdx.x;
    __shared__ float sred[8];
    __shared__ float sls;
    const int tid = threadIdx.x;  // 256
    float s = 0.f;
    for (int i = tid; i < 1000; i += 256)
        s += g_psum[(size_t)r * 1024 + i];
    #pragma unroll
    for (int o = 16; o; o >>= 1) s += __shfl_down_sync(~0u, s, o);
    if ((tid & 31) == 0) sred[tid >> 5] = s;
    __syncthreads();
    if (tid == 0) {
        float tot = 0.f;
        for (int w = 0; w < 8; w++) tot += sred[w];
        sls = logf(tot);
    }
    __syncthreads();
    float ls = sls;
    float* row = logp + (size_t)r * VV;
    for (int i = tid * 4; i < VV; i += 1024) {
        float4 v = *(float4*)(row + i);
        v.x -= ls; v.y -= ls; v.z -= ls; v.w -= ls;
        *(float4*)(row + i) = v;
    }
}

// ---------------- launcher ---------------------------------------------------------
extern "C" void kernel_launch(void* const* d_in, const int* in_sizes, int n_in,
                              void* d_out, int out_size)
{
    const float* enc   = (const float*)d_in[0];
    const float* ehid  = (const float*)d_in[1];
    const int*   tgt   = (const int*)  d_in[2];
    const float* emb   = (const float*)d_in[3];
    const float* Wa_w  = (const float*)d_in[4];
    const float* Wa_b  = (const float*)d_in[5];
    const float* Ua_w  = (const float*)d_in[6];
    const float* Ua_b  = (const float*)d_in[7];
    const float* Va_w  = (const float*)d_in[8];
    const float* Va_b  = (const float*)d_in[9];
    const float* W_ih  = (const float*)d_in[10];
    const float* b_ih  = (const float*)d_in[11];
    const float* W_hh  = (const float*)d_in[12];
    const float* b_hh  = (const float*)d_in[13];
    const float* Wh    = (const float*)d_in[14];
    const float* bh    = (const float*)d_in[15];
    const float* out_w = (const float*)d_in[16];
    const float* out_b = (const float*)d_in[17];

    float* outp = (float*)d_out;
    float* logp = outp;
    float* hfin = outp + (size_t)BB * TT * VV;
    float* attn = hfin + (size_t)BB * HH;

    float *hall, *eu, *gxe, *ctx, *part, *psum;
    int* tokp;
    __nv_bfloat16 *hbf, *wbf;
    cudaGetSymbolAddress((void**)&hall, g_Hall);
    cudaGetSymbolAddress((void**)&eu,   g_eu);
    cudaGetSymbolAddress((void**)&gxe,  g_gxe);
    cudaGetSymbolAddress((void**)&ctx,  g_ctx);
    cudaGetSymbolAddress((void**)&part, g_part);
    cudaGetSymbolAddress((void**)&psum, g_psum);
    cudaGetSymbolAddress((void**)&tokp, g_tok);
    cudaGetSymbolAddress((void**)&hbf,  g_Hbf);
    cudaGetSymbolAddress((void**)&wbf,  g_Wbf);

    tok_kernel<<<4, 256>>>(tgt);
    gemm_tn_kernel<<<dim3(4, 1), 256>>>(ehid, 2 * HH, Wh, 2 * HH, hall, HH, bh, 2 * HH);
    // e2u: fp32 (accuracy-critical)
    big128_kernel<<<dim3(16, 4), 256>>>(enc, 2 * HH, Ua_w, 2 * HH, Ua_b,
                                        2 * HH, eu, HH, 2);
    // gxe: bf16 HMMA (error negligible on tiny gate pre-activations)
    hmma_f32src_kernel<<<dim3(8, 12), 256>>>(emb, HH, tokp, W_ih, 3 * HH, b_ih,
                                             HH, gxe, 3 * HH);
    conv_bf16_kernel<<<4000, 256>>>(out_w, wbf, VV * HH / 4);

    for (int t = 0; t < TT; t++) {
        float* hcur = hall + (size_t)t * BB * HH;
        attn_step_kernel<<<BB, 512>>>(Wa_w, Wa_b, Va_w, Va_b, enc, b_hh, attn, t);
        pgemm_kernel<<<dim3(24, NSLICE), 128>>>(ctx, 2 * HH, W_ih + HH, 3 * HH,
                                                hcur, HH, W_hh, HH,
                                                4, 256, part, 3 * HH, BB * 3 * HH);
    }
    gates_kernel<<<BB, HH>>>(gxe + (size_t)31 * BB * 3 * HH, b_hh,
                             hall + (size_t)31 * BB * HH,
                             hbf + (size_t)31 * BB * HH, hfin);

    logits_hmma_kernel<<<dim3(8, 250), 256>>>(hbf, wbf, out_b, logp, psum);
    lsm_final_kernel<<<BB * TT, 256>>>(logp);
}

// round 16
// speedup vs baseline: 1.4081x; 1.0053x over previous
#include <cuda_runtime.h>
#include <cuda_bf16.h>
#include <math.h>
#include <stdint.h>

#define BB 32
#define SS 64
#define HH 512
#define TT 32
#define VV 32000
#define TILE_K 32
#define NSLICE 6

// ---------------- device scratch ------------------------------------------------
__device__ float g_Hall[(TT + 1) * BB * HH];
__device__ float g_eu[BB * SS * HH];
__device__ float g_gxe[TT * BB * 3 * HH];
__device__ float g_ctx[BB * 2 * HH];
__device__ float g_part[NSLICE * BB * 3 * HH];
__device__ float g_psum[(size_t)BB * TT * 1024];
__device__ int   g_tok[TT * BB];
__device__ __nv_bfloat16 g_Hbf[TT * BB * HH];
__device__ __nv_bfloat16 g_Wbf[(size_t)VV * HH];
__device__ __nv_bfloat16 g_Wabf[HH * HH];

typedef unsigned long long ull;
__device__ __forceinline__ void ffma2(ull& d, ull a, ull b) {
    asm("fma.rn.f32x2 %0, %1, %2, %0;" : "+l"(d) : "l"(a), "l"(b));
}
__device__ __forceinline__ ull dup2(float x) {
    ull r; asm("mov.b64 %0, {%1, %1};" : "=l"(r) : "f"(x)); return r;
}
__device__ __forceinline__ float2 unpack2(ull v) {
    float2 r; asm("mov.b64 {%0, %1}, %2;" : "=f"(r.x), "=f"(r.y) : "l"(v)); return r;
}
__device__ __forceinline__ float rcpf(float x) {
    float r; asm("rcp.approx.f32 %0, %1;" : "=f"(r) : "f"(x)); return r;
}
__device__ __forceinline__ float sig_f(float x) {
    x = fminf(fmaxf(x, -30.f), 30.f);
    return rcpf(1.f + __expf(-x));
}
__device__ __forceinline__ float tanh_f(float x) {
    x = fminf(fmaxf(x, -15.f), 15.f);
    float e = __expf(2.f * x);
    return 1.f - 2.f * rcpf(e + 1.f);
}
__device__ __forceinline__ uint32_t cvt_bf16x2(float hi, float lo) {
    uint32_t r;
    asm("cvt.rn.bf16x2.f32 %0, %1, %2;" : "=r"(r) : "f"(hi), "f"(lo));
    return r;
}
__device__ __forceinline__ float2 bf2f(uint32_t v) {
    return __bfloat1622float2(*(__nv_bfloat162*)&v);
}

// mma.sync m16n8k16 bf16 -> f32
__device__ __forceinline__ void mma16816(float* d, const uint32_t* a, const uint32_t* b) {
    asm volatile(
        "mma.sync.aligned.m16n8k16.row.col.f32.bf16.bf16.f32 "
        "{%0,%1,%2,%3}, {%4,%5,%6,%7}, {%8,%9}, {%0,%1,%2,%3};"
        : "+f"(d[0]), "+f"(d[1]), "+f"(d[2]), "+f"(d[3])
        : "r"(a[0]), "r"(a[1]), "r"(a[2]), "r"(a[3]), "r"(b[0]), "r"(b[1]));
}

// ---------------- bf16 converts ---------------------------------------------------
__global__ void conv_bf16_kernel(const float* __restrict__ src,
                                 __nv_bfloat16* __restrict__ dst, int n4)
{
    for (int i = blockIdx.x * blockDim.x + threadIdx.x; i < n4; i += gridDim.x * blockDim.x) {
        float4 v = *(const float4*)(src + (size_t)i * 4);
        uint2 o;
        o.x = cvt_bf16x2(v.y, v.x);
        o.y = cvt_bf16x2(v.w, v.z);
        *(uint2*)(dst + (size_t)i * 4) = o;
    }
}

// ---------------- tokens ----------------------------------------------------------
__global__ void tok_kernel(const int* __restrict__ tgt) {
    int i = blockIdx.x * 256 + threadIdx.x;
    if (i < TT * BB) {
        int t = i >> 5, b = i & 31;
        g_tok[i] = (t == 0) ? 0 : tgt[b * TT + t - 1];
    }
}

// ---------------- HMMA GEMM from fp32 sources (gxe) --------------------------------
#define SPAD 40
__global__ __launch_bounds__(256)
void hmma_f32src_kernel(const float* __restrict__ A, int lda,
                        const int* __restrict__ tokens,
                        const float* __restrict__ W, int ldw,
                        const float* __restrict__ bias, int K,
                        float* __restrict__ C, int ldc)
{
    __shared__ __align__(16) __nv_bfloat16 sA[128 * SPAD];
    __shared__ __align__(16) __nv_bfloat16 sB[128 * SPAD];
    __shared__ float sbias[128];
    const int tid = threadIdx.x;
    const int wid = tid >> 5, lane = tid & 31;
    const int m0 = blockIdx.x * 128;
    const int n0 = blockIdx.y * 128;
    if (tid < 128) sbias[tid] = bias[n0 + tid];

    const int lrow = tid >> 2;
    const int lc = tid & 3;
    long ar0 = tokens ? (long)tokens[m0 + lrow] : (long)(m0 + lrow);
    long ar1 = tokens ? (long)tokens[m0 + 64 + lrow] : (long)(m0 + 64 + lrow);
    const float* Ag0 = A + ar0 * lda + lc * 8;
    const float* Ag1 = A + ar1 * lda + lc * 8;
    const float* Bg0 = W + (size_t)(n0 + lrow) * ldw + lc * 8;
    const float* Bg1 = W + (size_t)(n0 + 64 + lrow) * ldw + lc * 8;
    __nv_bfloat16* sA0 = sA + lrow * SPAD + lc * 8;
    __nv_bfloat16* sA1 = sA0 + 64 * SPAD;
    __nv_bfloat16* sB0 = sB + lrow * SPAD + lc * 8;
    __nv_bfloat16* sB1 = sB0 + 64 * SPAD;

    const int mw = (wid >> 2) * 64, nw = (wid & 3) * 32;
    const int qr = lane >> 2, qc = lane & 3;
    const __nv_bfloat16* pa = sA + (mw + qr) * SPAD + qc * 2;
    const __nv_bfloat16* pb = sB + (nw + qr) * SPAD + qc * 2;

    float acc[4][4][4];
    #pragma unroll
    for (int i = 0; i < 4; i++)
        #pragma unroll
        for (int j = 0; j < 4; j++)
            #pragma unroll
            for (int e = 0; e < 4; e++) acc[i][j][e] = 0.f;

    const int kTiles = K / 32;
    #pragma unroll 1
    for (int kt = 0; kt < kTiles; kt++) {
        int ko = kt * 32;
        float4 a0l = *(const float4*)(Ag0 + ko);
        float4 a0h = *(const float4*)(Ag0 + ko + 4);
        float4 a1l = *(const float4*)(Ag1 + ko);
        float4 a1h = *(const float4*)(Ag1 + ko + 4);
        float4 b0l = *(const float4*)(Bg0 + ko);
        float4 b0h = *(const float4*)(Bg0 + ko + 4);
        float4 b1l = *(const float4*)(Bg1 + ko);
        float4 b1h = *(const float4*)(Bg1 + ko + 4);
        uint4 pa0, pa1, pb0, pb1;
        pa0.x = cvt_bf16x2(a0l.y, a0l.x); pa0.y = cvt_bf16x2(a0l.w, a0l.z);
        pa0.z = cvt_bf16x2(a0h.y, a0h.x); pa0.w = cvt_bf16x2(a0h.w, a0h.z);
        pa1.x = cvt_bf16x2(a1l.y, a1l.x); pa1.y = cvt_bf16x2(a1l.w, a1l.z);
        pa1.z = cvt_bf16x2(a1h.y, a1h.x); pa1.w = cvt_bf16x2(a1h.w, a1h.z);
        pb0.x = cvt_bf16x2(b0l.y, b0l.x); pb0.y = cvt_bf16x2(b0l.w, b0l.z);
        pb0.z = cvt_bf16x2(b0h.y, b0h.x); pb0.w = cvt_bf16x2(b0h.w, b0h.z);
        pb1.x = cvt_bf16x2(b1l.y, b1l.x); pb1.y = cvt_bf16x2(b1l.w, b1l.z);
        pb1.z = cvt_bf16x2(b1h.y, b1h.x); pb1.w = cvt_bf16x2(b1h.w, b1h.z);
        *(uint4*)sA0 = pa0; *(uint4*)sA1 = pa1;
        *(uint4*)sB0 = pb0; *(uint4*)sB1 = pb1;
        __syncthreads();
        #pragma unroll
        for (int ks = 0; ks < 2; ks++) {
            uint32_t af[4][4], bf[4][2];
            #pragma unroll
            for (int mi = 0; mi < 4; mi++) {
                const __nv_bfloat16* p2 = pa + mi * 16 * SPAD + ks * 16;
                af[mi][0] = *(const uint32_t*)(p2);
                af[mi][1] = *(const uint32_t*)(p2 + 8 * SPAD);
                af[mi][2] = *(const uint32_t*)(p2 + 8);
                af[mi][3] = *(const uint32_t*)(p2 + 8 * SPAD + 8);
            }
            #pragma unroll
            for (int ni = 0; ni < 4; ni++) {
                const __nv_bfloat16* p2 = pb + ni * 8 * SPAD + ks * 16;
                bf[ni][0] = *(const uint32_t*)(p2);
                bf[ni][1] = *(const uint32_t*)(p2 + 8);
            }
            #pragma unroll
            for (int mi = 0; mi < 4; mi++)
                #pragma unroll
                for (int ni = 0; ni < 4; ni++)
                    mma16816(acc[mi][ni], af[mi], bf[ni]);
        }
        __syncthreads();
    }

    #pragma unroll
    for (int mi = 0; mi < 4; mi++) {
        const int rA = m0 + mw + mi * 16 + qr;
        const int rB = rA + 8;
        float* cpA = C + (size_t)rA * ldc + n0;
        float* cpB = C + (size_t)rB * ldc + n0;
        #pragma unroll
        for (int ni = 0; ni < 4; ni++) {
            const int cl = nw + ni * 8 + qc * 2;
            *(float2*)(cpA + cl) = make_float2(acc[mi][ni][0] + sbias[cl],
                                               acc[mi][ni][1] + sbias[cl + 1]);
            *(float2*)(cpB + cl) = make_float2(acc[mi][ni][2] + sbias[cl],
                                               acc[mi][ni][3] + sbias[cl + 1]);
        }
    }
}

// ---------------- split-K partial GEMM (loop GRU): 6 slices of k=256 ---------------
__global__ void pgemm_kernel(const float* __restrict__ A1, int lda1,
                             const float* __restrict__ W1, int ldw1,
                             const float* __restrict__ A2, int lda2,
                             const float* __restrict__ W2, int ldw2,
                             int slices1, int kPerSlice,
                             float* __restrict__ out, int ldo, int sliceStride)
{
    __shared__ float sxh[TILE_K][33];
    __shared__ float sw[TILE_K][68];
    const int tid = threadIdx.x;
    const int s = blockIdx.y;
    const int n0 = blockIdx.x * 64;
    const float* a; int la; const float* w; int lw;
    if (s < slices1) { a = A1 + s * kPerSlice; la = lda1; w = W1 + s * kPerSlice; lw = ldw1; }
    else { int s2 = s - slices1; a = A2 + s2 * kPerSlice; la = lda2; w = W2 + s2 * kPerSlice; lw = ldw2; }
    const int kTiles = kPerSlice / TILE_K;
    const int lb = tid >> 2, lk = (tid & 3) * 4;
    const int ln = tid >> 3, lk8 = (tid & 7) * 4;
    const int vq = tid & 15, bg = tid >> 4;

    float4 ra[2], rw[4];
    #pragma unroll
    for (int it = 0; it < 2; it++)
        ra[it] = *(const float4*)(a + (size_t)lb * la + lk + 16 * it);
    #pragma unroll
    for (int it = 0; it < 4; it++)
        rw[it] = *(const float4*)(w + (size_t)(n0 + ln + 16 * it) * lw + lk8);

    float acc[4][4] = {};
    for (int kt = 0; kt < kTiles; kt++) {
        #pragma unroll
        for (int it = 0; it < 2; it++) {
            int kk = lk + 16 * it;
            sxh[kk + 0][lb] = ra[it].x; sxh[kk + 1][lb] = ra[it].y;
            sxh[kk + 2][lb] = ra[it].z; sxh[kk + 3][lb] = ra[it].w;
        }
        #pragma unroll
        for (int it = 0; it < 4; it++) {
            int n = ln + 16 * it;
            sw[lk8 + 0][n] = rw[it].x; sw[lk8 + 1][n] = rw[it].y;
            sw[lk8 + 2][n] = rw[it].z; sw[lk8 + 3][n] = rw[it].w;
        }
        __syncthreads();
        if (kt + 1 < kTiles) {
            int ko = (kt + 1) * TILE_K;
            #pragma unroll
            for (int it = 0; it < 2; it++)
                ra[it] = *(const float4*)(a + (size_t)lb * la + ko + lk + 16 * it);
            #pragma unroll
            for (int it = 0; it < 4; it++)
                rw[it] = *(const float4*)(w + (size_t)(n0 + ln + 16 * it) * lw + ko + lk8);
        }
        #pragma unroll 8
        for (int k = 0; k < TILE_K; k++) {
            float4 wv = *(const float4*)(&sw[k][vq * 4]);
            float a0 = sxh[k][bg * 4 + 0], a1 = sxh[k][bg * 4 + 1];
            float a2 = sxh[k][bg * 4 + 2], a3 = sxh[k][bg * 4 + 3];
            acc[0][0] += wv.x * a0; acc[0][1] += wv.x * a1; acc[0][2] += wv.x * a2; acc[0][3] += wv.x * a3;
            acc[1][0] += wv.y * a0; acc[1][1] += wv.y * a1; acc[1][2] += wv.y * a2; acc[1][3] += wv.y * a3;
            acc[2][0] += wv.z * a0; acc[2][1] += wv.z * a1; acc[2][2] += wv.z * a2; acc[2][3] += wv.z * a3;
            acc[3][0] += wv.w * a0; acc[3][1] += wv.w * a1; acc[3][2] += wv.w * a2; acc[3][3] += wv.w * a3;
        }
        __syncthreads();
    }
    #pragma unroll
    for (int j = 0; j < 4; j++) {
        int b = bg * 4 + j;
        *(float4*)(out + (size_t)s * sliceStride + (size_t)b * ldo + n0 + vq * 4) =
            make_float4(acc[0][j], acc[1][j], acc[2][j], acc[3][j]);
    }
}

// ---------------- fused per-step attention (bf16 Wa stream; enc/eu fp32) ----------
__global__ void attn_step_kernel(const __nv_bfloat16* __restrict__ Wa_bf,
                                 const float* __restrict__ Wa_b,
                                 const float* __restrict__ Va_w,
                                 const float* __restrict__ Va_b,
                                 const float* __restrict__ enc,
                                 const float* __restrict__ b_hh,
                                 float* __restrict__ attn_out, int t)
{
    __shared__ __align__(16) float sh_h[HH];
    __shared__ __align__(16) float se[HH];
    __shared__ __align__(16) float sva[HH];
    __shared__ float ssc[SS];
    __shared__ float sms[2];
    const int b = blockIdx.x;
    const int tid = threadIdx.x;
    const int warp = tid >> 5, lane = tid & 31;

    if (t > 0) {
        const int j = tid;
        const float* p0 = g_part + (size_t)(0 * BB + b) * (3 * HH);
        const float* p1 = g_part + (size_t)(1 * BB + b) * (3 * HH);
        const float* p2 = g_part + (size_t)(2 * BB + b) * (3 * HH);
        const float* p3 = g_part + (size_t)(3 * BB + b) * (3 * HH);
        const float* p4 = g_part + (size_t)(4 * BB + b) * (3 * HH);
        const float* p5 = g_part + (size_t)(5 * BB + b) * (3 * HH);
        const float* ge = g_gxe + ((size_t)(t - 1) * BB + b) * (3 * HH);
        float gx_r = ge[j] + p0[j] + p1[j] + p2[j] + p3[j];
        float gh_r = p4[j] + p5[j] + b_hh[j];
        float gx_z = ge[j + HH] + p0[j + HH] + p1[j + HH] + p2[j + HH] + p3[j + HH];
        float gh_z = p4[j + HH] + p5[j + HH] + b_hh[j + HH];
        float gx_n = ge[j + 2 * HH] + p0[j + 2 * HH] + p1[j + 2 * HH] + p2[j + 2 * HH] + p3[j + 2 * HH];
        float gh_n = p4[j + 2 * HH] + p5[j + 2 * HH] + b_hh[j + 2 * HH];
        float r = sig_f(gx_r + gh_r);
        float z = sig_f(gx_z + gh_z);
        float n = tanh_f(gx_n + r * gh_n);
        float hp = g_Hall[(size_t)(t - 1) * BB * HH + b * HH + j];
        float hn = (1.f - z) * n + z * hp;
        sh_h[j] = hn;
        g_Hall[(size_t)t * BB * HH + b * HH + j] = hn;
        g_Hbf[(size_t)(t - 1) * BB * HH + b * HH + j] = __float2bfloat16(hn);
    } else {
        sh_h[tid] = g_Hall[b * HH + tid];
    }
    sva[tid] = Va_w[tid];
    __syncthreads();

    // q rows: 2 rows per iteration, Wa in bf16 (half the stream), math fp32
    const float4* sh4 = (const float4*)sh_h;
    for (int rr = 0; rr < 32; rr += 2) {
        int i0 = warp * 32 + rr;
        int i1 = i0 + 1;
        const uint4* w0 = (const uint4*)(Wa_bf + (size_t)i0 * HH);
        const uint4* w1 = (const uint4*)(Wa_bf + (size_t)i1 * HH);
        float s0 = 0.f, s1 = 0.f;
        #pragma unroll
        for (int it = 0; it < 2; it++) {
            int c = lane + 32 * it;             // 16B chunk = 8 bf16
            uint4 a0 = __ldcg(w0 + c);
            uint4 a1 = __ldcg(w1 + c);
            float4 h0 = sh4[2 * c], h1 = sh4[2 * c + 1];
            float2 p;
            p = bf2f(a0.x); s0 += p.x * h0.x + p.y * h0.y;
            p = bf2f(a0.y); s0 += p.x * h0.z + p.y * h0.w;
            p = bf2f(a0.z); s0 += p.x * h1.x + p.y * h1.y;
            p = bf2f(a0.w); s0 += p.x * h1.z + p.y * h1.w;
            p = bf2f(a1.x); s1 += p.x * h0.x + p.y * h0.y;
            p = bf2f(a1.y); s1 += p.x * h0.z + p.y * h0.w;
            p = bf2f(a1.z); s1 += p.x * h1.x + p.y * h1.y;
            p = bf2f(a1.w); s1 += p.x * h1.z + p.y * h1.w;
        }
        #pragma unroll
        for (int o = 16; o; o >>= 1) {
            s0 += __shfl_xor_sync(~0u, s0, o);
            s1 += __shfl_xor_sync(~0u, s1, o);
        }
        if (lane == 0) {
            se[i0] = __expf(2.f * (s0 + Wa_b[i0]));
            se[i1] = __expf(2.f * (s1 + Wa_b[i1]));
        }
    }
    __syncthreads();

    // scores: 2 s per iteration, eu fp32 (accuracy-critical)
    const float4* se4 = (const float4*)se;
    const float4* sva4 = (const float4*)sva;
    for (int ss = 0; ss < 4; ss += 2) {
        int s0i = warp * 4 + ss;
        int s1i = s0i + 1;
        const float4* eu0 = (const float4*)(g_eu + (size_t)(b * SS + s0i) * HH);
        const float4* eu1 = (const float4*)(g_eu + (size_t)(b * SS + s1i) * HH);
        float s0 = 0.f, s1 = 0.f;
        #pragma unroll
        for (int it = 0; it < 4; it++) {
            int idx = lane + 32 * it;
            float4 e0 = __ldcg(eu0 + idx);
            float4 e1 = __ldcg(eu1 + idx);
            float4 q4 = se4[idx];
            float4 v4 = sva4[idx];
            s0 += v4.x * (1.f - 2.f * rcpf(q4.x * e0.x + 1.f));
            s0 += v4.y * (1.f - 2.f * rcpf(q4.y * e0.y + 1.f));
            s0 += v4.z * (1.f - 2.f * rcpf(q4.z * e0.z + 1.f));
            s0 += v4.w * (1.f - 2.f * rcpf(q4.w * e0.w + 1.f));
            s1 += v4.x * (1.f - 2.f * rcpf(q4.x * e1.x + 1.f));
            s1 += v4.y * (1.f - 2.f * rcpf(q4.y * e1.y + 1.f));
            s1 += v4.z * (1.f - 2.f * rcpf(q4.z * e1.z + 1.f));
            s1 += v4.w * (1.f - 2.f * rcpf(q4.w * e1.w + 1.f));
        }
        #pragma unroll
        for (int o = 16; o; o >>= 1) {
            s0 += __shfl_xor_sync(~0u, s0, o);
            s1 += __shfl_xor_sync(~0u, s1, o);
        }
        if (lane == 0) {
            ssc[s0i] = s0 + Va_b[0];
            ssc[s1i] = s1 + Va_b[0];
        }
    }
    __syncthreads();

    if (tid == 0) {
        float m = ssc[0];
        for (int s = 1; s < SS; s++) m = fmaxf(m, ssc[s]);
        float sm = 0.f;
        for (int s = 0; s < SS; s++) sm += __expf(ssc[s] - m);
        sms[0] = m; sms[1] = rcpf(sm);
    }
    __syncthreads();
    if (tid < SS) {
        float w = __expf(ssc[tid] - sms[0]) * sms[1];
        ssc[tid] = w;
        attn_out[((size_t)b * TT + t) * SS + tid] = w;
    }
    __syncthreads();

    // ctx: enc fp32 (accuracy-critical), 2 outputs/thread
    for (int kk = tid; kk < 2 * HH; kk += 512) {
        float a = 0.f;
        #pragma unroll 8
        for (int s = 0; s < SS; s++)
            a += ssc[s] * enc[(size_t)(b * SS + s) * (2 * HH) + kk];
        g_ctx[b * 2 * HH + kk] = a;
    }
}

// ---------------- final gates (h_32 -> hfin + hbf) ---------------------------------
__global__ void gates_kernel(const float* __restrict__ gxe_t,
                             const float* __restrict__ b_hh,
                             const float* __restrict__ h_old,
                             __nv_bfloat16* __restrict__ hbf_t,
                             float* __restrict__ hfin)
{
    const int b = blockIdx.x;
    const int j = threadIdx.x;
    const float* p0 = g_part + (size_t)(0 * BB + b) * (3 * HH);
    const float* p1 = g_part + (size_t)(1 * BB + b) * (3 * HH);
    const float* p2 = g_part + (size_t)(2 * BB + b) * (3 * HH);
    const float* p3 = g_part + (size_t)(3 * BB + b) * (3 * HH);
    const float* p4 = g_part + (size_t)(4 * BB + b) * (3 * HH);
    const float* p5 = g_part + (size_t)(5 * BB + b) * (3 * HH);
    const float* ge = gxe_t + (size_t)b * (3 * HH);
    float gx_r = ge[j] + p0[j] + p1[j] + p2[j] + p3[j];
    float gh_r = p4[j] + p5[j] + b_hh[j];
    float gx_z = ge[j + HH] + p0[j + HH] + p1[j + HH] + p2[j + HH] + p3[j + HH];
    float gh_z = p4[j + HH] + p5[j + HH] + b_hh[j + HH];
    float gx_n = ge[j + 2 * HH] + p0[j + 2 * HH] + p1[j + 2 * HH] + p2[j + 2 * HH] + p3[j + 2 * HH];
    float gh_n = p4[j + 2 * HH] + p5[j + 2 * HH] + b_hh[j + 2 * HH];
    float r = sig_f(gx_r + gh_r);
    float z = sig_f(gx_z + gh_z);
    float n = tanh_f(gx_n + r * gh_n);
    float hv = (1.f - z) * n + z * h_old[b * HH + j];
    hbf_t[b * HH + j] = __float2bfloat16(hv);
    hfin[b * HH + j] = hv;
}

// ---------------- logits: bf16 HMMA GEMM + fused exp psum -------------------------
__global__ __launch_bounds__(256)
void logits_hmma_kernel(const __nv_bfloat16* __restrict__ Hbf,
                        const __nv_bfloat16* __restrict__ Wbf,
                        const float* __restrict__ out_b,
                        float* __restrict__ logp, float* __restrict__ psum)
{
    __shared__ __align__(16) __nv_bfloat16 sA[128 * SPAD];
    __shared__ __align__(16) __nv_bfloat16 sB[128 * SPAD];
    __shared__ float sbias[128];
    const int tid = threadIdx.x;
    const int wid = tid >> 5, lane = tid & 31;
    const int m0 = blockIdx.x * 128;
    const int n0 = blockIdx.y * 128;
    if (tid < 128) sbias[tid] = out_b[n0 + tid];

    const int lrow = tid >> 2;
    const int lc = tid & 3;
    const __nv_bfloat16* Ag0 = Hbf + (size_t)(m0 + lrow) * HH + lc * 8;
    const __nv_bfloat16* Ag1 = Ag0 + (size_t)64 * HH;
    const __nv_bfloat16* Bg0 = Wbf + (size_t)(n0 + lrow) * HH + lc * 8;
    const __nv_bfloat16* Bg1 = Bg0 + (size_t)64 * HH;
    __nv_bfloat16* sA0 = sA + lrow * SPAD + lc * 8;
    __nv_bfloat16* sA1 = sA0 + 64 * SPAD;
    __nv_bfloat16* sB0 = sB + lrow * SPAD + lc * 8;
    __nv_bfloat16* sB1 = sB0 + 64 * SPAD;

    uint4 ra0 = *(const uint4*)Ag0;
    uint4 ra1 = *(const uint4*)Ag1;
    uint4 rb0 = *(const uint4*)Bg0;
    uint4 rb1 = *(const uint4*)Bg1;

    const int mw = (wid >> 2) * 64, nw = (wid & 3) * 32;
    const int qr = lane >> 2, qc = lane & 3;
    const __nv_bfloat16* pa = sA + (mw + qr) * SPAD + qc * 2;
    const __nv_bfloat16* pb = sB + (nw + qr) * SPAD + qc * 2;

    float acc[4][4][4];
    #pragma unroll
    for (int i = 0; i < 4; i++)
        #pragma unroll
        for (int j = 0; j < 4; j++)
            #pragma unroll
            for (int e = 0; e < 4; e++) acc[i][j][e] = 0.f;

    #pragma unroll 1
    for (int kt = 0; kt < 16; kt++) {
        *(uint4*)sA0 = ra0; *(uint4*)sA1 = ra1;
        *(uint4*)sB0 = rb0; *(uint4*)sB1 = rb1;
        __syncthreads();
        if (kt < 15) {
            ra0 = *(const uint4*)(Ag0 + (kt + 1) * 32);
            ra1 = *(const uint4*)(Ag1 + (kt + 1) * 32);
            rb0 = *(const uint4*)(Bg0 + (kt + 1) * 32);
            rb1 = *(const uint4*)(Bg1 + (kt + 1) * 32);
        }
        #pragma unroll
        for (int ks = 0; ks < 2; ks++) {
            uint32_t af[4][4], bf[4][2];
            #pragma unroll
            for (int mi = 0; mi < 4; mi++) {
                const __nv_bfloat16* p2 = pa + mi * 16 * SPAD + ks * 16;
                af[mi][0] = *(const uint32_t*)(p2);
                af[mi][1] = *(const uint32_t*)(p2 + 8 * SPAD);
                af[mi][2] = *(const uint32_t*)(p2 + 8);
                af[mi][3] = *(const uint32_t*)(p2 + 8 * SPAD + 8);
            }
            #pragma unroll
            for (int ni = 0; ni < 4; ni++) {
                const __nv_bfloat16* p2 = pb + ni * 8 * SPAD + ks * 16;
                bf[ni][0] = *(const uint32_t*)(p2);
                bf[ni][1] = *(const uint32_t*)(p2 + 8);
            }
            #pragma unroll
            for (int mi = 0; mi < 4; mi++)
                #pragma unroll
                for (int ni = 0; ni < 4; ni++)
                    mma16816(acc[mi][ni], af[mi], bf[ni]);
        }
        __syncthreads();
    }

    float es[8];
    #pragma unroll
    for (int i = 0; i < 8; i++) es[i] = 0.f;

    #pragma unroll
    for (int mi = 0; mi < 4; mi++) {
        const int rA = m0 + mw + mi * 16 + qr;
        const int rB = rA + 8;
        const int tqA = rA >> 5, bqA = rA & 31;
        const int tqB = rB >> 5, bqB = rB & 31;
        float* cpA = logp + (size_t)(bqA * TT + tqA) * VV + n0;
        float* cpB = logp + (size_t)(bqB * TT + tqB) * VV + n0;
        #pragma unroll
        for (int ni = 0; ni < 4; ni++) {
            const int cl = nw + ni * 8 + qc * 2;
            float v0 = acc[mi][ni][0] + sbias[cl];
            float v1 = acc[mi][ni][1] + sbias[cl + 1];
            float v2 = acc[mi][ni][2] + sbias[cl];
            float v3 = acc[mi][ni][3] + sbias[cl + 1];
            *(float2*)(cpA + cl) = make_float2(v0, v1);
            *(float2*)(cpB + cl) = make_float2(v2, v3);
            es[mi * 2 + 0] += __expf(v0) + __expf(v1);
            es[mi * 2 + 1] += __expf(v2) + __expf(v3);
        }
    }
    #pragma unroll
    for (int i = 0; i < 8; i++) {
        es[i] += __shfl_xor_sync(0xffffffffu, es[i], 1);
        es[i] += __shfl_xor_sync(0xffffffffu, es[i], 2);
    }
    if (qc == 0) {
        const int col = blockIdx.y * 4 + (wid & 3);
        #pragma unroll
        for (int mi = 0; mi < 4; mi++) {
            int rA = m0 + mw + mi * 16 + qr;
            int rB = rA + 8;
            int rowA = (rA & 31) * TT + (rA >> 5);
            int rowB = (rB & 31) * TT + (rB >> 5);
            psum[(size_t)rowA * 1024 + col] = es[mi * 2 + 0];
            psum[(size_t)rowB * 1024 + col] = es[mi * 2 + 1];
        }
    }
}

// ---------------- fp32 big GEMM (e2u only, accuracy-critical) ----------------------
__global__ __launch_bounds__(256, 2)
void big128_kernel(const float* __restrict__ A, int lda,
                   const float* __restrict__ W, int ldw,
                   const float* __restrict__ bias, int K,
                   float* __restrict__ C, int ldc, int mode)
{
    __shared__ __align__(16) float sA[16][132];
    __shared__ __align__(16) float sB[16][132];
    const int tid = threadIdx.x;
    const int m0 = blockIdx.x * 128;
    const int n0 = blockIdx.y * 128;
    const int tx4 = (tid & 15) * 4;
    const int ty4 = (tid >> 4) * 4;

    const int row0 = tid >> 2,         kq0 = (tid & 3) * 4;
    const int row1 = (tid + 256) >> 2;
    const float* ap0 = A + (size_t)(m0 + row0) * lda + kq0;
    const float* ap1 = A + (size_t)(m0 + row1) * lda + kq0;
    const float* wp0 = W + (size_t)(n0 + row0) * ldw + kq0;
    const float* wp1 = W + (size_t)(n0 + row1) * ldw + kq0;

    float4 ra0 = *(const float4*)ap0;
    float4 ra1 = *(const float4*)ap1;
    float4 rw0 = *(const float4*)wp0;
    float4 rw1 = *(const float4*)wp1;

    ull acc[4][8];
    #pragma unroll
    for (int i = 0; i < 4; i++)
        #pragma unroll
        for (int j = 0; j < 8; j++) acc[i][j] = 0ull;

    const int kTiles = K / 16;
    for (int kt = 0; kt < kTiles; kt++) {
        sA[kq0 + 0][row0] = ra0.x; sA[kq0 + 1][row0] = ra0.y;
        sA[kq0 + 2][row0] = ra0.z; sA[kq0 + 3][row0] = ra0.w;
        sA[kq0 + 0][row1] = ra1.x; sA[kq0 + 1][row1] = ra1.y;
        sA[kq0 + 2][row1] = ra1.z; sA[kq0 + 3][row1] = ra1.w;
        sB[kq0 + 0][row0] = rw0.x; sB[kq0 + 1][row0] = rw0.y;
        sB[kq0 + 2][row0] = rw0.z; sB[kq0 + 3][row0] = rw0.w;
        sB[kq0 + 0][row1] = rw1.x; sB[kq0 + 1][row1] = rw1.y;
        sB[kq0 + 2][row1] = rw1.z; sB[kq0 + 3][row1] = rw1.w;
        __syncthreads();
        if (kt + 1 < kTiles) {
            int ko = (kt + 1) * 16;
            ra0 = *(const float4*)(ap0 + ko);
            ra1 = *(const float4*)(ap1 + ko);
            rw0 = *(const float4*)(wp0 + ko);
            rw1 = *(const float4*)(wp1 + ko);
        }
        #pragma unroll
        for (int k = 0; k < 16; k++) {
            ulonglong2 a0 = *(const ulonglong2*)&sA[k][ty4];
            ulonglong2 a1 = *(const ulonglong2*)&sA[k][64 + ty4];
            float4 b0 = *(const float4*)&sB[k][tx4];
            float4 b1 = *(const float4*)&sB[k][64 + tx4];
            ull ap[4] = {a0.x, a0.y, a1.x, a1.y};
            ull bd[8] = {dup2(b0.x), dup2(b0.y), dup2(b0.z), dup2(b0.w),
                         dup2(b1.x), dup2(b1.y), dup2(b1.z), dup2(b1.w)};
            #pragma unroll
            for (int mp = 0; mp < 4; mp++)
                #pragma unroll
                for (int n = 0; n < 8; n++)
                    ffma2(acc[mp][n], ap[mp], bd[n]);
        }
        __syncthreads();
    }

    float4 bs0 = *(const float4*)&bias[n0 + tx4];
    float4 bs1 = *(const float4*)&bias[n0 + 64 + tx4];
    #pragma unroll
    for (int mp = 0; mp < 4; mp++) {
        #pragma unroll
        for (int half = 0; half < 2; half++) {
            int gm = m0 + (mp >> 1) * 64 + ty4 + (mp & 1) * 2 + half;
            float v[8];
            #pragma unroll
            for (int n = 0; n < 8; n++) {
                float2 p = unpack2(acc[mp][n]);
                v[n] = half ? p.y : p.x;
            }
            v[0] += bs0.x; v[1] += bs0.y; v[2] += bs0.z; v[3] += bs0.w;
            v[4] += bs1.x; v[5] += bs1.y; v[6] += bs1.z; v[7] += bs1.w;
            if (mode == 2) {
                #pragma unroll
                for (int n = 0; n < 8; n++) v[n] = __expf(2.f * v[n]);
            }
            float* cp = C + (size_t)gm * ldc + n0;
            *(float4*)(cp + tx4)      = make_float4(v[0], v[1], v[2], v[3]);
            *(float4*)(cp + 64 + tx4) = make_float4(v[4], v[5], v[6], v[7]);
        }
    }
}

// ---------------- small gemm (h0 only) --------------------------------------------
__global__ void gemm_tn_kernel(const float* __restrict__ A, int lda,
                               const float* __restrict__ W, int ldb,
                               float* __restrict__ C, int ldc,
                               const float* __restrict__ bias, int K)
{
    __shared__ float sa[TILE_K][33];
    __shared__ float sb[TILE_K][132];
    const int tid = threadIdx.x;
    const int n0 = blockIdx.x * 128;
    const int vq = tid & 31, bg = tid >> 5;
    const int lm = tid >> 3, lk = (tid & 7) * 4;
    float acc[4][4] = {};
    for (int k0 = 0; k0 < K; k0 += TILE_K) {
        float4 a4 = *(const float4*)(A + (size_t)lm * lda + k0 + lk);
        sa[lk + 0][lm] = a4.x; sa[lk + 1][lm] = a4.y;
        sa[lk + 2][lm] = a4.z; sa[lk + 3][lm] = a4.w;
        #pragma unroll
        for (int it = 0; it < 4; it++) {
            int n = lm + 32 * it;
            float4 b4 = *(const float4*)(W + (size_t)(n0 + n) * ldb + k0 + lk);
            sb[lk + 0][n] = b4.x; sb[lk + 1][n] = b4.y;
            sb[lk + 2][n] = b4.z; sb[lk + 3][n] = b4.w;
        }
        __syncthreads();
        #pragma unroll 8
        for (int k = 0; k < TILE_K; k++) {
            float4 bv = *(const float4*)(&sb[k][vq * 4]);
            float a0 = sa[k][bg * 4 + 0], a1 = sa[k][bg * 4 + 1];
            float a2 = sa[k][bg * 4 + 2], a3 = sa[k][bg * 4 + 3];
            acc[0][0] += bv.x * a0; acc[0][1] += bv.x * a1; acc[0][2] += bv.x * a2; acc[0][3] += bv.x * a3;
            acc[1][0] += bv.y * a0; acc[1][1] += bv.y * a1; acc[1][2] += bv.y * a2; acc[1][3] += bv.y * a3;
            acc[2][0] += bv.z * a0; acc[2][1] += bv.z * a1; acc[2][2] += bv.z * a2; acc[2][3] += bv.z * a3;
            acc[3][0] += bv.w * a0; acc[3][1] += bv.w * a1; acc[3][2] += bv.w * a2; acc[3][3] += bv.w * a3;
        }
        __syncthreads();
    }
    float4 bs4 = *(const float4*)(bias + n0 + vq * 4);
    #pragma unroll
    for (int j = 0; j < 4; j++) {
        float4 o;
        o.x = acc[0][j] + bs4.x; o.y = acc[1][j] + bs4.y;
        o.z = acc[2][j] + bs4.z; o.w = acc[3][j] + bs4.w;
        *(float4*)(C + (size_t)(bg * 4 + j) * ldc + n0 + vq * 4) = o;
    }
}

__global__ void lsm_final_kernel(float* __restrict__ logp)
{
    const int r = blockIdx.x;
    __shared__ float sred[8];
    __shared__ float sls;
    const int tid = threadIdx.x;  // 256
    float s = 0.f;
    for (int i = tid; i < 1000; i += 256)
        s += g_psum[(size_t)r * 1024 + i];
    #pragma unroll
    for (int o = 16; o; o >>= 1) s += __shfl_down_sync(~0u, s, o);
    if ((tid & 31) == 0) sred[tid >> 5] = s;
    __syncthreads();
    if (tid == 0) {
        float tot = 0.f;
        for (int w = 0; w < 8; w++) tot += sred[w];
        sls = logf(tot);
    }
    __syncthreads();
    float ls = sls;
    float* row = logp + (size_t)r * VV;
    for (int i = tid * 4; i < VV; i += 1024) {
        float4 v = *(float4*)(row + i);
        v.x -= ls; v.y -= ls; v.z -= ls; v.w -= ls;
        *(float4*)(row + i) = v;
    }
}

// ---------------- launcher ---------------------------------------------------------
extern "C" void kernel_launch(void* const* d_in, const int* in_sizes, int n_in,
                              void* d_out, int out_size)
{
    const float* enc   = (const float*)d_in[0];
    const float* ehid  = (const float*)d_in[1];
    const int*   tgt   = (const int*)  d_in[2];
    const float* emb   = (const float*)d_in[3];
    const float* Wa_w  = (const float*)d_in[4];
    const float* Wa_b  = (const float*)d_in[5];
    const float* Ua_w  = (const float*)d_in[6];
    const float* Ua_b  = (const float*)d_in[7];
    const float* Va_w  = (const float*)d_in[8];
    const float* Va_b  = (const float*)d_in[9];
    const float* W_ih  = (const float*)d_in[10];
    const float* b_ih  = (const float*)d_in[11];
    const float* W_hh  = (const float*)d_in[12];
    const float* b_hh  = (const float*)d_in[13];
    const float* Wh    = (const float*)d_in[14];
    const float* bh    = (const float*)d_in[15];
    const float* out_w = (const float*)d_in[16];
    const float* out_b = (const float*)d_in[17];

    float* outp = (float*)d_out;
    float* logp = outp;
    float* hfin = outp + (size_t)BB * TT * VV;
    float* attn = hfin + (size_t)BB * HH;

    float *hall, *eu, *gxe, *ctx, *part, *psum;
    int* tokp;
    __nv_bfloat16 *hbf, *wbf, *wabf;
    cudaGetSymbolAddress((void**)&hall, g_Hall);
    cudaGetSymbolAddress((void**)&eu,   g_eu);
    cudaGetSymbolAddress((void**)&gxe,  g_gxe);
    cudaGetSymbolAddress((void**)&ctx,  g_ctx);
    cudaGetSymbolAddress((void**)&part, g_part);
    cudaGetSymbolAddress((void**)&psum, g_psum);
    cudaGetSymbolAddress((void**)&tokp, g_tok);
    cudaGetSymbolAddress((void**)&hbf,  g_Hbf);
    cudaGetSymbolAddress((void**)&wbf,  g_Wbf);
    cudaGetSymbolAddress((void**)&wabf, g_Wabf);

    tok_kernel<<<4, 256>>>(tgt);
    gemm_tn_kernel<<<dim3(4, 1), 256>>>(ehid, 2 * HH, Wh, 2 * HH, hall, HH, bh, 2 * HH);
    // e2u: fp32 (accuracy-critical: feeds attn weights directly)
    big128_kernel<<<dim3(16, 4), 256>>>(enc, 2 * HH, Ua_w, 2 * HH, Ua_b,
                                        2 * HH, eu, HH, 2);
    // gxe: bf16 HMMA
    hmma_f32src_kernel<<<dim3(8, 12), 256>>>(emb, HH, tokp, W_ih, 3 * HH, b_ih,
                                             HH, gxe, 3 * HH);
    conv_bf16_kernel<<<4000, 256>>>(out_w, wbf, VV * HH / 4);
    conv_bf16_kernel<<<256, 256>>>(Wa_w, wabf, HH * HH / 4);

    for (int t = 0; t < TT; t++) {
        float* hcur = hall + (size_t)t * BB * HH;
        attn_step_kernel<<<BB, 512>>>(wabf, Wa_b, Va_w, Va_b, enc, b_hh, attn, t);
        pgemm_kernel<<<dim3(24, NSLICE), 128>>>(ctx, 2 * HH, W_ih + HH, 3 * HH,
                                                hcur, HH, W_hh, HH,
                                                4, 256, part, 3 * HH, BB * 3 * HH);
    }
    gates_kernel<<<BB, HH>>>(gxe + (size_t)31 * BB * 3 * HH, b_hh,
                             hall + (size_t)31 * BB * HH,
                             hbf + (size_t)31 * BB * HH, hfin);

    logits_hmma_kernel<<<dim3(8, 250), 256>>>(hbf, wbf, out_b, logp, psum);
    lsm_final_kernel<<<BB * TT, 256>>>(logp);
}